// round 2
// baseline (speedup 1.0000x reference)
#include <cuda_runtime.h>
#include <math.h>

// Problem constants
#define BATCH   4
#define SEQ     512
#define D_DIM   512
#define V_DIM   32000
#define BS_ROWS (BATCH * SEQ)   // 2048
#define GAMMA_F 0.5f
#define EPS_F   1e-12f

// ---------------------------------------------------------------------------
// Static scratch (no cudaMalloc allowed)
// ---------------------------------------------------------------------------
__device__ float              g_vinv[V_DIM];                 // 1/max(||emb_v||, eps)
__device__ float              g_outn[BS_ROWS * D_DIM];       // L2-normalized preds rows
__device__ float              g_q   [BS_ROWS * D_DIM];       // out_norm - emb[target]
__device__ unsigned long long g_best[BS_ROWS];               // packed (score, idx) argmax
__device__ float              g_diff[BS_ROWS];               // per-row masked hinge

// Monotone float->uint mapping; key = score<<32 | (0x7fffffff - idx)
// -> atomicMax picks larger score, and on exact tie the SMALLER index
//    (matches jnp.argmax first-occurrence semantics).
__device__ __forceinline__ unsigned long long enc_key(float v, unsigned idx) {
    unsigned u = __float_as_uint(v);
    u = (u & 0x80000000u) ? ~u : (u | 0x80000000u);
    return ((unsigned long long)u << 32) | (unsigned long long)(0x7fffffffu - idx);
}

__device__ __forceinline__ int clamp_idx(int t) {
    t = t < 0 ? 0 : t;
    return t >= V_DIM ? V_DIM - 1 : t;
}

// ---------------------------------------------------------------------------
// Kernel 1: per-vocab inverse norms. One warp per vocab row.
// ---------------------------------------------------------------------------
__global__ void vnorm_kernel(const float* __restrict__ emb) {
    int gw   = (blockIdx.x * blockDim.x + threadIdx.x) >> 5;
    int lane = threadIdx.x & 31;
    if (gw >= V_DIM) return;
    const float* row = emb + (size_t)gw * D_DIM;
    float ss = 0.f;
#pragma unroll
    for (int d = lane; d < D_DIM; d += 32) { float x = row[d]; ss = fmaf(x, x, ss); }
#pragma unroll
    for (int off = 16; off; off >>= 1) ss += __shfl_xor_sync(0xffffffffu, ss, off);
    if (lane == 0) g_vinv[gw] = 1.f / fmaxf(sqrtf(ss), EPS_F);
}

// ---------------------------------------------------------------------------
// Kernel 2: build out_norm and q = out_norm - emb[target]. One block per row.
// preds is [B, D, S]; row r=(b,s) reads a strided column over d.
// Also resets g_best for this row (must happen every call: graph replays).
// ---------------------------------------------------------------------------
__global__ void prep_kernel(const float* __restrict__ preds,
                            const float* __restrict__ emb,
                            const int* __restrict__ target) {
    __shared__ float red[128];
    int r = blockIdx.x;
    int b = r >> 9, s = r & 511;                 // SEQ = 512
    const float* col = preds + ((size_t)b * D_DIM * SEQ + s);
    float v[4]; float ss = 0.f;
#pragma unroll
    for (int i = 0; i < 4; i++) {
        int d = threadIdx.x + i * 128;
        v[i] = col[(size_t)d * SEQ];
        ss = fmaf(v[i], v[i], ss);
    }
    red[threadIdx.x] = ss; __syncthreads();
    for (int off = 64; off; off >>= 1) {
        if (threadIdx.x < off) red[threadIdx.x] += red[threadIdx.x + off];
        __syncthreads();
    }
    float inv = 1.f / fmaxf(sqrtf(red[0]), EPS_F);
    int t = clamp_idx(target[r]);
    const float* erow = emb + (size_t)t * D_DIM;
#pragma unroll
    for (int i = 0; i < 4; i++) {
        int d = threadIdx.x + i * 128;
        float on = v[i] * inv;
        g_outn[(size_t)r * D_DIM + d] = on;
        g_q   [(size_t)r * D_DIM + d] = on - erow[d];
    }
    if (threadIdx.x == 0) g_best[r] = 0ull;
}

// ---------------------------------------------------------------------------
// Kernel 3: fused GEMM + argmax.  score[r,v] = (q[r] . emb[v]) * vinv[v]
// 128x128 tile, BK=16, 256 threads, 8x8 per thread. Cross-tile argmax via
// atomicMax on packed keys.
// ---------------------------------------------------------------------------
#define BM 128
#define BN 128
#define BK 16

__global__ void __launch_bounds__(256)
gemm_argmax_kernel(const float* __restrict__ emb) {
    __shared__ float As[BK][BM];
    __shared__ float Bs[BK][BN + 4];

    const int mblk = blockIdx.x * BM;
    const int nblk = blockIdx.y * BN;
    const int tid  = threadIdx.x;
    const int tx   = tid & 15;
    const int ty   = tid >> 4;
    const int lr   = tid >> 2;           // 0..63
    const int lc   = (tid & 3) << 2;     // 0,4,8,12

    float acc[8][8];
#pragma unroll
    for (int i = 0; i < 8; i++)
#pragma unroll
        for (int j = 0; j < 8; j++) acc[i][j] = 0.f;

    for (int k0 = 0; k0 < D_DIM; k0 += BK) {
#pragma unroll
        for (int rr = 0; rr < 2; rr++) {
            int row = lr + rr * 64;
            float4 av = *(const float4*)&g_q[(size_t)(mblk + row) * D_DIM + k0 + lc];
            As[lc + 0][row] = av.x; As[lc + 1][row] = av.y;
            As[lc + 2][row] = av.z; As[lc + 3][row] = av.w;
            float4 bv = *(const float4*)&emb[(size_t)(nblk + row) * D_DIM + k0 + lc];
            Bs[lc + 0][row] = bv.x; Bs[lc + 1][row] = bv.y;
            Bs[lc + 2][row] = bv.z; Bs[lc + 3][row] = bv.w;
        }
        __syncthreads();
#pragma unroll
        for (int k = 0; k < BK; k++) {
            float a[8], bb[8];
            *(float4*)&a[0]  = *(const float4*)&As[k][ty * 8];
            *(float4*)&a[4]  = *(const float4*)&As[k][ty * 8 + 4];
            *(float4*)&bb[0] = *(const float4*)&Bs[k][tx * 8];
            *(float4*)&bb[4] = *(const float4*)&Bs[k][tx * 8 + 4];
#pragma unroll
            for (int i = 0; i < 8; i++)
#pragma unroll
                for (int j = 0; j < 8; j++)
                    acc[i][j] = fmaf(a[i], bb[j], acc[i][j]);
        }
        __syncthreads();
    }

    // epilogue: scale by vinv, per-row argmax within the tile, then atomicMax
    float vin[8];
#pragma unroll
    for (int j = 0; j < 8; j++) vin[j] = g_vinv[nblk + tx * 8 + j];

#pragma unroll
    for (int i = 0; i < 8; i++) {
        float bv = acc[i][0] * vin[0];
        int   bj = nblk + tx * 8;
#pragma unroll
        for (int j = 1; j < 8; j++) {
            float sc = acc[i][j] * vin[j];
            if (sc > bv) { bv = sc; bj = nblk + tx * 8 + j; }
        }
        // reduce across the 16 threads (same ty) sharing this row
#pragma unroll
        for (int off = 8; off; off >>= 1) {
            float ov = __shfl_xor_sync(0xffffffffu, bv, off);
            int   oj = __shfl_xor_sync(0xffffffffu, bj, off);
            if (ov > bv || (ov == bv && oj < bj)) { bv = ov; bj = oj; }
        }
        if (tx == 0)
            atomicMax(&g_best[mblk + ty * 8 + i], enc_key(bv, (unsigned)bj));
    }
}

// ---------------------------------------------------------------------------
// Kernel 4: per-row hinge. One warp per row.
// cos_target = out_norm . voc_norm[target];  cos_j = out_norm . voc_norm[jmax]
// ---------------------------------------------------------------------------
__global__ void finalize_kernel(const float* __restrict__ emb,
                                const int* __restrict__ target,
                                const int* __restrict__ pad) {
    int r    = blockIdx.x * 8 + (threadIdx.x >> 5);
    int lane = threadIdx.x & 31;
    int t = clamp_idx(target[r]);
    unsigned long long key = g_best[r];
    int jm = clamp_idx((int)(0x7fffffffu - (unsigned)(key & 0xffffffffu)));

    const float* on = g_outn + (size_t)r * D_DIM;
    const float* e1 = emb + (size_t)t  * D_DIM;
    const float* e2 = emb + (size_t)jm * D_DIM;
    float d1 = 0.f, d2 = 0.f;
#pragma unroll
    for (int d = lane; d < D_DIM; d += 32) {
        float o = on[d];
        d1 = fmaf(o, e1[d], d1);
        d2 = fmaf(o, e2[d], d2);
    }
#pragma unroll
    for (int off = 16; off; off >>= 1) {
        d1 += __shfl_xor_sync(0xffffffffu, d1, off);
        d2 += __shfl_xor_sync(0xffffffffu, d2, off);
    }
    if (lane == 0) {
        d1 *= g_vinv[t];
        d2 *= g_vinv[jm];
        float df = fmaxf(GAMMA_F + d2 - d1, 0.f);
        g_diff[r] = (target[r] != *pad) ? df : 0.f;
    }
}

// ---------------------------------------------------------------------------
// Kernel 5: single-block deterministic reduction -> scalar loss
// ---------------------------------------------------------------------------
__global__ void reduce_kernel(const int* __restrict__ target,
                              const int* __restrict__ pad,
                              float* __restrict__ out) {
    __shared__ float ssum[1024];
    __shared__ float scnt[1024];
    int t = threadIdx.x;
    int p = *pad;
    float s = 0.f, c = 0.f;
    for (int r = t; r < BS_ROWS; r += 1024) {
        s += g_diff[r];
        c += (target[r] != p) ? 1.f : 0.f;
    }
    ssum[t] = s; scnt[t] = c; __syncthreads();
    for (int off = 512; off; off >>= 1) {
        if (t < off) { ssum[t] += ssum[t + off]; scnt[t] += scnt[t + off]; }
        __syncthreads();
    }
    if (t == 0) out[0] = ssum[0] / scnt[0];
}

// ---------------------------------------------------------------------------
extern "C" void kernel_launch(void* const* d_in, const int* in_sizes, int n_in,
                              void* d_out, int out_size) {
    const float* preds  = (const float*)d_in[0];
    const float* emb    = (const float*)d_in[1];
    const int*   target = (const int*)d_in[2];   // JAX downcasts int64->int32 (x64 off)
    const int*   pad    = (const int*)d_in[3];

    vnorm_kernel<<<V_DIM / 8, 256>>>(emb);                 // 4000 blocks, warp/row
    prep_kernel<<<BS_ROWS, 128>>>(preds, emb, target);     // also resets g_best
    dim3 grid(BS_ROWS / BM, V_DIM / BN);                   // (16, 250)
    gemm_argmax_kernel<<<grid, 256>>>(emb);
    finalize_kernel<<<BS_ROWS / 8, 256>>>(emb, target, pad);
    reduce_kernel<<<1, 1024>>>(target, pad, (float*)d_out);
}

// round 4
// speedup vs baseline: 2.2531x; 2.2531x over previous
#include <cuda_runtime.h>
#include <cuda_bf16.h>
#include <math.h>
#include <stdint.h>

// Problem constants
#define D_DIM   512
#define V_DIM   32000
#define BS_ROWS 2048
#define GAMMA_F 0.5f
#define EPS_F   1e-12f

// GEMM tiling
#define MT 128
#define NT 256
#define KC 64               // bf16 K per chunk (128 B rows)
#define NCHUNK 24           // 3 passes * (512/64)

// SMEM: rows padded to 72 bf16 (144 B) for conflict-free ldmatrix
#define ROWB   144
#define ABUF   (MT * ROWB)          // 18432
#define BBUF   (NT * ROWB)          // 36864
#define STAGE  (ABUF + BBUF)        // 55296
#define SMEMSZ (2 * STAGE)          // 110592

// ---------------------------------------------------------------------------
// Static scratch
// ---------------------------------------------------------------------------
__device__ __nv_bfloat16 g_qh[BS_ROWS * D_DIM];
__device__ __nv_bfloat16 g_ql[BS_ROWS * D_DIM];
__device__ __nv_bfloat16 g_eh[(size_t)V_DIM * D_DIM];
__device__ __nv_bfloat16 g_el[(size_t)V_DIM * D_DIM];
__device__ float              g_vinv[V_DIM];
__device__ float              g_outn[BS_ROWS * D_DIM];
__device__ unsigned long long g_best[BS_ROWS];
__device__ float              g_diff[BS_ROWS];

// ---------------------------------------------------------------------------
// helpers
// ---------------------------------------------------------------------------
__device__ __forceinline__ uint32_t smem_u32(const void* p) {
    uint32_t a;
    asm("{ .reg .u64 t; cvta.to.shared.u64 t, %1; cvt.u32.u64 %0, t; }" : "=r"(a) : "l"(p));
    return a;
}
__device__ __forceinline__ void cp16(uint32_t dst, const void* src) {
    asm volatile("cp.async.cg.shared.global [%0], [%1], 16;" :: "r"(dst), "l"(src));
}
#define CP_COMMIT() asm volatile("cp.async.commit_group;" ::: "memory")
#define CP_WAIT1()  asm volatile("cp.async.wait_group 1;" ::: "memory")
#define CP_WAIT0()  asm volatile("cp.async.wait_group 0;" ::: "memory")

__device__ __forceinline__ void ldsm_x4(uint32_t addr, uint32_t& r0, uint32_t& r1,
                                        uint32_t& r2, uint32_t& r3) {
    asm volatile("ldmatrix.sync.aligned.m8n8.x4.shared.b16 {%0,%1,%2,%3}, [%4];"
                 : "=r"(r0), "=r"(r1), "=r"(r2), "=r"(r3) : "r"(addr));
}
__device__ __forceinline__ void mma16816(float* c, const uint32_t* a, const uint32_t* b) {
    asm volatile(
        "mma.sync.aligned.m16n8k16.row.col.f32.bf16.bf16.f32 "
        "{%0,%1,%2,%3}, {%4,%5,%6,%7}, {%8,%9}, {%0,%1,%2,%3};"
        : "+f"(c[0]), "+f"(c[1]), "+f"(c[2]), "+f"(c[3])
        : "r"(a[0]), "r"(a[1]), "r"(a[2]), "r"(a[3]), "r"(b[0]), "r"(b[1]));
}

// Monotone (score, idx) packing; bigger score wins, tie -> smaller index
__device__ __forceinline__ unsigned long long enc_key(float v, unsigned idx) {
    unsigned u = __float_as_uint(v);
    u = (u & 0x80000000u) ? ~u : (u | 0x80000000u);
    return ((unsigned long long)u << 32) | (unsigned long long)(0x7fffffffu - idx);
}
__device__ __forceinline__ int clamp_idx(int t) {
    t = t < 0 ? 0 : t;
    return t >= V_DIM ? V_DIM - 1 : t;
}

// ---------------------------------------------------------------------------
// Kernel 1: vocab pass — vinv + bf16 hi/lo split. One block(128) per row.
// ---------------------------------------------------------------------------
__global__ void vsplit_kernel(const float* __restrict__ emb) {
    __shared__ float red[128];
    int r = blockIdx.x;
    const float4* row = (const float4*)(emb + (size_t)r * D_DIM);
    float4 v = row[threadIdx.x];
    float ss = v.x * v.x + v.y * v.y + v.z * v.z + v.w * v.w;
    red[threadIdx.x] = ss; __syncthreads();
    for (int off = 64; off; off >>= 1) {
        if (threadIdx.x < off) red[threadIdx.x] += red[threadIdx.x + off];
        __syncthreads();
    }
    if (threadIdx.x == 0) g_vinv[r] = 1.f / fmaxf(sqrtf(red[0]), EPS_F);

    size_t base = (size_t)r * D_DIM + threadIdx.x * 4;
    float x[4] = {v.x, v.y, v.z, v.w};
    __nv_bfloat16 h[4], l[4];
#pragma unroll
    for (int i = 0; i < 4; i++) {
        h[i] = __float2bfloat16_rn(x[i]);
        l[i] = __float2bfloat16_rn(x[i] - __bfloat162float(h[i]));
    }
    *(__nv_bfloat162*)(g_eh + base)     = __halves2bfloat162(h[0], h[1]);
    *(__nv_bfloat162*)(g_eh + base + 2) = __halves2bfloat162(h[2], h[3]);
    *(__nv_bfloat162*)(g_el + base)     = __halves2bfloat162(l[0], l[1]);
    *(__nv_bfloat162*)(g_el + base + 2) = __halves2bfloat162(l[2], l[3]);
}

// ---------------------------------------------------------------------------
// Kernel 2: out_norm + q split. One block(128) per row. Resets g_best.
// ---------------------------------------------------------------------------
__global__ void prep_kernel(const float* __restrict__ preds,
                            const float* __restrict__ emb,
                            const int* __restrict__ target) {
    __shared__ float red[128];
    int r = blockIdx.x;
    int b = r >> 9, s = r & 511;
    const float* col = preds + ((size_t)b * D_DIM * 512 + s);
    float v[4]; float ss = 0.f;
#pragma unroll
    for (int i = 0; i < 4; i++) {
        int d = threadIdx.x + i * 128;
        v[i] = col[(size_t)d * 512];
        ss = fmaf(v[i], v[i], ss);
    }
    red[threadIdx.x] = ss; __syncthreads();
    for (int off = 64; off; off >>= 1) {
        if (threadIdx.x < off) red[threadIdx.x] += red[threadIdx.x + off];
        __syncthreads();
    }
    float inv = 1.f / fmaxf(sqrtf(red[0]), EPS_F);
    int t = clamp_idx(target[r]);
    const float* erow = emb + (size_t)t * D_DIM;
#pragma unroll
    for (int i = 0; i < 4; i++) {
        int d = threadIdx.x + i * 128;
        float on = v[i] * inv;
        g_outn[(size_t)r * D_DIM + d] = on;
        float q = on - erow[d];
        __nv_bfloat16 h = __float2bfloat16_rn(q);
        g_qh[(size_t)r * D_DIM + d] = h;
        g_ql[(size_t)r * D_DIM + d] = __float2bfloat16_rn(q - __bfloat162float(h));
    }
    if (threadIdx.x == 0) g_best[r] = 0ull;
}

// ---------------------------------------------------------------------------
// Kernel 3: mma.sync bf16 GEMM (3-product split, fused accumulation) + argmax.
// CTA 128x256, 8 warps (warp tile 64x64), cp.async double buffer.
// ---------------------------------------------------------------------------
__global__ void __launch_bounds__(256, 1) gemm_mma_kernel() {
    extern __shared__ char smem[];
    const uint32_t sb = smem_u32(smem);
    const int tid  = threadIdx.x;
    const int wid  = tid >> 5;
    const int lane = tid & 31;
    const int mblk = blockIdx.x * MT;
    const int nblk = blockIdx.y * NT;
    const int warp_m = (wid & 1) * 64;
    const int warp_n = (wid >> 1) * 64;

    const __nv_bfloat16* Ap[3] = {g_qh + (size_t)mblk * D_DIM,
                                  g_ql + (size_t)mblk * D_DIM,
                                  g_qh + (size_t)mblk * D_DIM};
    const __nv_bfloat16* Bp[3] = {g_eh + (size_t)nblk * D_DIM,
                                  g_eh + (size_t)nblk * D_DIM,
                                  g_el + (size_t)nblk * D_DIM};

    // issue cp.async for one chunk into stage buf
    auto load_chunk = [&](int buf, int ch) {
        int p  = ch >> 3;
        int kc = (ch & 7) * KC;
        const __nv_bfloat16* A = Ap[p] + kc;
        const __nv_bfloat16* B = Bp[p] + kc;
        uint32_t sa = sb + buf * STAGE;
        uint32_t sbm = sa + ABUF;
        // A: 128 rows * 8 segs(16B) = 1024 -> 4 per thread
#pragma unroll
        for (int i = 0; i < 4; i++) {
            int s = tid + i * 256;
            int row = s >> 3, c = s & 7;
            cp16(sa + row * ROWB + c * 16, A + (size_t)row * D_DIM + c * 8);
        }
        // B: 256 rows * 8 segs = 2048 -> 8 per thread
#pragma unroll
        for (int i = 0; i < 8; i++) {
            int s = tid + i * 256;
            int row = s >> 3, c = s & 7;
            cp16(sbm + row * ROWB + c * 16, B + (size_t)row * D_DIM + c * 8);
        }
    };

    float acc[4][8][4];
#pragma unroll
    for (int i = 0; i < 4; i++)
#pragma unroll
        for (int j = 0; j < 8; j++)
#pragma unroll
            for (int k = 0; k < 4; k++) acc[i][j][k] = 0.f;

    load_chunk(0, 0);
    CP_COMMIT();

    for (int it = 0; it < NCHUNK; it++) {
        if (it + 1 < NCHUNK) {
            load_chunk((it + 1) & 1, it + 1);
            CP_COMMIT();
            CP_WAIT1();
        } else {
            CP_WAIT0();
        }
        __syncthreads();

        uint32_t sa  = sb + (it & 1) * STAGE;
        uint32_t sbm = sa + ABUF;
#pragma unroll
        for (int ks = 0; ks < 4; ks++) {
            int k = ks * 16;
            uint32_t a[4][4];
#pragma unroll
            for (int mi = 0; mi < 4; mi++) {
                int row = warp_m + mi * 16 + (lane & 15);
                int ko  = k + (lane >> 4) * 8;
                ldsm_x4(sa + row * ROWB + ko * 2, a[mi][0], a[mi][1], a[mi][2], a[mi][3]);
            }
            uint32_t b[8][2];
#pragma unroll
            for (int nj = 0; nj < 4; nj++) {
                int n = warp_n + nj * 16 + (lane & 7) + ((lane >> 4) & 1) * 8;
                int ko = k + ((lane >> 3) & 1) * 8;
                ldsm_x4(sbm + n * ROWB + ko * 2,
                        b[nj * 2][0], b[nj * 2][1], b[nj * 2 + 1][0], b[nj * 2 + 1][1]);
            }
#pragma unroll
            for (int mi = 0; mi < 4; mi++)
#pragma unroll
                for (int nj = 0; nj < 8; nj++)
                    mma16816(acc[mi][nj], a[mi], b[nj]);
        }
        __syncthreads();
    }

    // stage vinv for this N tile
    ((float*)smem)[tid] = g_vinv[nblk + tid];
    __syncthreads();
    const float* vin = (const float*)smem;

    // argmax epilogue: rows r0 = warp_m + mi*16 + lane/4 (+8), cols warp_n + nj*8 + 2*(lane&3)
#pragma unroll
    for (int mi = 0; mi < 4; mi++) {
        float bv0 = -1e30f, bv1 = -1e30f;
        int   bj0 = 0,      bj1 = 0;
#pragma unroll
        for (int nj = 0; nj < 8; nj++) {
            int c0 = warp_n + nj * 8 + 2 * (lane & 3);
            float v00 = acc[mi][nj][0] * vin[c0];
            float v01 = acc[mi][nj][1] * vin[c0 + 1];
            float v10 = acc[mi][nj][2] * vin[c0];
            float v11 = acc[mi][nj][3] * vin[c0 + 1];
            if (v00 > bv0) { bv0 = v00; bj0 = c0; }
            if (v01 > bv0) { bv0 = v01; bj0 = c0 + 1; }
            if (v10 > bv1) { bv1 = v10; bj1 = c0; }
            if (v11 > bv1) { bv1 = v11; bj1 = c0 + 1; }
        }
        // reduce across the 4 lanes sharing each row (lane&3)
#pragma unroll
        for (int off = 1; off < 4; off <<= 1) {
            float o0 = __shfl_xor_sync(0xffffffffu, bv0, off);
            int   j0 = __shfl_xor_sync(0xffffffffu, bj0, off);
            float o1 = __shfl_xor_sync(0xffffffffu, bv1, off);
            int   j1 = __shfl_xor_sync(0xffffffffu, bj1, off);
            if (o0 > bv0 || (o0 == bv0 && j0 < bj0)) { bv0 = o0; bj0 = j0; }
            if (o1 > bv1 || (o1 == bv1 && j1 < bj1)) { bv1 = o1; bj1 = j1; }
        }
        if ((lane & 3) == 0) {
            int r0 = mblk + warp_m + mi * 16 + (lane >> 2);
            atomicMax(&g_best[r0],     enc_key(bv0, (unsigned)(nblk + bj0)));
            atomicMax(&g_best[r0 + 8], enc_key(bv1, (unsigned)(nblk + bj1)));
        }
    }
}

// ---------------------------------------------------------------------------
// Kernel 4: per-row hinge in exact fp32. One warp per row.
// ---------------------------------------------------------------------------
__global__ void finalize_kernel(const float* __restrict__ emb,
                                const int* __restrict__ target,
                                const int* __restrict__ pad) {
    int r    = blockIdx.x * 8 + (threadIdx.x >> 5);
    int lane = threadIdx.x & 31;
    int t = clamp_idx(target[r]);
    unsigned long long key = g_best[r];
    int jm = clamp_idx((int)(0x7fffffffu - (unsigned)(key & 0xffffffffu)));

    const float* on = g_outn + (size_t)r * D_DIM;
    const float* e1 = emb + (size_t)t  * D_DIM;
    const float* e2 = emb + (size_t)jm * D_DIM;
    float d1 = 0.f, d2 = 0.f;
#pragma unroll
    for (int d = lane; d < D_DIM; d += 32) {
        float o = on[d];
        d1 = fmaf(o, e1[d], d1);
        d2 = fmaf(o, e2[d], d2);
    }
#pragma unroll
    for (int off = 16; off; off >>= 1) {
        d1 += __shfl_xor_sync(0xffffffffu, d1, off);
        d2 += __shfl_xor_sync(0xffffffffu, d2, off);
    }
    if (lane == 0) {
        d1 *= g_vinv[t];
        d2 *= g_vinv[jm];
        float df = fmaxf(GAMMA_F + d2 - d1, 0.f);
        g_diff[r] = (target[r] != *pad) ? df : 0.f;
    }
}

// ---------------------------------------------------------------------------
// Kernel 5: deterministic scalar reduction
// ---------------------------------------------------------------------------
__global__ void reduce_kernel(const int* __restrict__ target,
                              const int* __restrict__ pad,
                              float* __restrict__ out) {
    __shared__ float ssum[1024];
    __shared__ float scnt[1024];
    int t = threadIdx.x;
    int p = *pad;
    float s = 0.f, c = 0.f;
    for (int r = t; r < BS_ROWS; r += 1024) {
        s += g_diff[r];
        c += (target[r] != p) ? 1.f : 0.f;
    }
    ssum[t] = s; scnt[t] = c; __syncthreads();
    for (int off = 512; off; off >>= 1) {
        if (t < off) { ssum[t] += ssum[t + off]; scnt[t] += scnt[t + off]; }
        __syncthreads();
    }
    if (t == 0) out[0] = ssum[0] / scnt[0];
}

// ---------------------------------------------------------------------------
extern "C" void kernel_launch(void* const* d_in, const int* in_sizes, int n_in,
                              void* d_out, int out_size) {
    const float* preds  = (const float*)d_in[0];
    const float* emb    = (const float*)d_in[1];
    const int*   target = (const int*)d_in[2];
    const int*   pad    = (const int*)d_in[3];

    cudaFuncSetAttribute(gemm_mma_kernel, cudaFuncAttributeMaxDynamicSharedMemorySize, SMEMSZ);

    vsplit_kernel<<<V_DIM, 128>>>(emb);
    prep_kernel<<<BS_ROWS, 128>>>(preds, emb, target);
    dim3 grid(BS_ROWS / MT, V_DIM / NT);   // (16, 125)
    gemm_mma_kernel<<<grid, 256, SMEMSZ>>>();
    finalize_kernel<<<BS_ROWS / 8, 256>>>(emb, target, pad);
    reduce_kernel<<<1, 1024>>>(target, pad, (float*)d_out);
}

// round 5
// speedup vs baseline: 3.6835x; 1.6349x over previous
#include <cuda_runtime.h>
#include <cuda_fp16.h>
#include <math.h>
#include <stdint.h>

// Problem constants
#define D_DIM   512
#define V_DIM   32000
#define BS_ROWS 2048
#define GAMMA_F 0.5f
#define EPS_F   1e-12f

// GEMM tiling
#define MT 128
#define NT 256
#define KC 64               // fp16 K per chunk (128 B rows)
#define NCHUNK 8            // 512 / 64
#define NSTAGE 3

// SMEM: rows padded to 72 halves (144 B) for conflict-free ldmatrix
#define ROWB   144
#define AQH_OFF 0
#define AQL_OFF (MT * ROWB)              // 18432
#define B_OFF   (2 * MT * ROWB)          // 36864
#define STAGE   (2 * MT * ROWB + NT * ROWB)   // 73728
#define SMEMSZ  (NSTAGE * STAGE)         // 221184

// ---------------------------------------------------------------------------
// Static scratch
// ---------------------------------------------------------------------------
__device__ __half g_qh[BS_ROWS * D_DIM];
__device__ __half g_ql[BS_ROWS * D_DIM];
__device__ __half g_eh[(size_t)V_DIM * D_DIM];
__device__ float              g_vinv[V_DIM];
__device__ float              g_outn[BS_ROWS * D_DIM];
__device__ unsigned long long g_best[BS_ROWS];
__device__ float              g_diff[BS_ROWS];

// ---------------------------------------------------------------------------
// helpers
// ---------------------------------------------------------------------------
__device__ __forceinline__ uint32_t smem_u32(const void* p) {
    uint32_t a;
    asm("{ .reg .u64 t; cvta.to.shared.u64 t, %1; cvt.u32.u64 %0, t; }" : "=r"(a) : "l"(p));
    return a;
}
__device__ __forceinline__ void cp16(uint32_t dst, const void* src) {
    asm volatile("cp.async.cg.shared.global [%0], [%1], 16;" :: "r"(dst), "l"(src));
}
#define CP_COMMIT() asm volatile("cp.async.commit_group;" ::: "memory")
#define CP_WAIT1()  asm volatile("cp.async.wait_group 1;" ::: "memory")
#define CP_WAIT0()  asm volatile("cp.async.wait_group 0;" ::: "memory")

__device__ __forceinline__ void ldsm_x4(uint32_t addr, uint32_t& r0, uint32_t& r1,
                                        uint32_t& r2, uint32_t& r3) {
    asm volatile("ldmatrix.sync.aligned.m8n8.x4.shared.b16 {%0,%1,%2,%3}, [%4];"
                 : "=r"(r0), "=r"(r1), "=r"(r2), "=r"(r3) : "r"(addr));
}
__device__ __forceinline__ void mma16816(float* c, const uint32_t* a, const uint32_t* b) {
    asm volatile(
        "mma.sync.aligned.m16n8k16.row.col.f32.f16.f16.f32 "
        "{%0,%1,%2,%3}, {%4,%5,%6,%7}, {%8,%9}, {%0,%1,%2,%3};"
        : "+f"(c[0]), "+f"(c[1]), "+f"(c[2]), "+f"(c[3])
        : "r"(a[0]), "r"(a[1]), "r"(a[2]), "r"(a[3]), "r"(b[0]), "r"(b[1]));
}

// Monotone (score, idx) packing; bigger score wins, tie -> smaller index
__device__ __forceinline__ unsigned long long enc_key(float v, unsigned idx) {
    unsigned u = __float_as_uint(v);
    u = (u & 0x80000000u) ? ~u : (u | 0x80000000u);
    return ((unsigned long long)u << 32) | (unsigned long long)(0x7fffffffu - idx);
}
__device__ __forceinline__ int clamp_idx(int t) {
    t = t < 0 ? 0 : t;
    return t >= V_DIM ? V_DIM - 1 : t;
}

// ---------------------------------------------------------------------------
// Kernel 1: vocab pass — vinv + fp16 copy. One block(128) per row.
// ---------------------------------------------------------------------------
__global__ void vsplit_kernel(const float* __restrict__ emb) {
    __shared__ float red[128];
    int r = blockIdx.x;
    const float4* row = (const float4*)(emb + (size_t)r * D_DIM);
    float4 v = row[threadIdx.x];
    float ss = v.x * v.x + v.y * v.y + v.z * v.z + v.w * v.w;
    red[threadIdx.x] = ss; __syncthreads();
    for (int off = 64; off; off >>= 1) {
        if (threadIdx.x < off) red[threadIdx.x] += red[threadIdx.x + off];
        __syncthreads();
    }
    if (threadIdx.x == 0) g_vinv[r] = 1.f / fmaxf(sqrtf(red[0]), EPS_F);

    size_t base = (size_t)r * D_DIM + threadIdx.x * 4;
    *(__half2*)(g_eh + base)     = __halves2half2(__float2half_rn(v.x), __float2half_rn(v.y));
    *(__half2*)(g_eh + base + 2) = __halves2half2(__float2half_rn(v.z), __float2half_rn(v.w));
}

// ---------------------------------------------------------------------------
// Kernel 2: out_norm + q = out_norm - emb[target], fp16 hi/lo split.
// One block(128) per row. Resets g_best.
// ---------------------------------------------------------------------------
__global__ void prep_kernel(const float* __restrict__ preds,
                            const float* __restrict__ emb,
                            const int* __restrict__ target) {
    __shared__ float red[128];
    int r = blockIdx.x;
    int b = r >> 9, s = r & 511;
    const float* col = preds + ((size_t)b * D_DIM * 512 + s);
    float v[4]; float ss = 0.f;
#pragma unroll
    for (int i = 0; i < 4; i++) {
        int d = threadIdx.x + i * 128;
        v[i] = col[(size_t)d * 512];
        ss = fmaf(v[i], v[i], ss);
    }
    red[threadIdx.x] = ss; __syncthreads();
    for (int off = 64; off; off >>= 1) {
        if (threadIdx.x < off) red[threadIdx.x] += red[threadIdx.x + off];
        __syncthreads();
    }
    float inv = 1.f / fmaxf(sqrtf(red[0]), EPS_F);
    int t = clamp_idx(target[r]);
    const float* erow = emb + (size_t)t * D_DIM;
#pragma unroll
    for (int i = 0; i < 4; i++) {
        int d = threadIdx.x + i * 128;
        float on = v[i] * inv;
        g_outn[(size_t)r * D_DIM + d] = on;
        float q = on - erow[d];
        __half h = __float2half_rn(q);
        g_qh[(size_t)r * D_DIM + d] = h;
        g_ql[(size_t)r * D_DIM + d] = __float2half_rn(q - __half2float(h));
    }
    if (threadIdx.x == 0) g_best[r] = 0ull;
}

// ---------------------------------------------------------------------------
// Kernel 3: fp16 mma.sync GEMM, 2 A-operands sharing one B, 3-stage cp.async,
// fused vinv-scale + argmax. CTA 128x256, 8 warps (warp tile 64x64).
// ---------------------------------------------------------------------------
__global__ void __launch_bounds__(256, 1) gemm_mma_kernel() {
    extern __shared__ char smem[];
    const uint32_t sb = smem_u32(smem);
    const int tid  = threadIdx.x;
    const int wid  = tid >> 5;
    const int lane = tid & 31;
    const int mblk = blockIdx.x * MT;
    const int nblk = blockIdx.y * NT;
    const int warp_m = (wid & 1) * 64;
    const int warp_n = (wid >> 1) * 64;

    const __half* Aqh = g_qh + (size_t)mblk * D_DIM;
    const __half* Aql = g_ql + (size_t)mblk * D_DIM;
    const __half* Beh = g_eh + (size_t)nblk * D_DIM;

    auto load_chunk = [&](int slot, int ch) {
        int kc = ch * KC;
        uint32_t st = sb + slot * STAGE;
        // A_qh + A_ql: 128 rows * 8 segs each -> 4+4 per thread
#pragma unroll
        for (int i = 0; i < 4; i++) {
            int s = tid + i * 256;
            int row = s >> 3, c = s & 7;
            cp16(st + AQH_OFF + row * ROWB + c * 16, Aqh + (size_t)row * D_DIM + kc + c * 8);
            cp16(st + AQL_OFF + row * ROWB + c * 16, Aql + (size_t)row * D_DIM + kc + c * 8);
        }
        // B: 256 rows * 8 segs = 2048 -> 8 per thread
#pragma unroll
        for (int i = 0; i < 8; i++) {
            int s = tid + i * 256;
            int row = s >> 3, c = s & 7;
            cp16(st + B_OFF + row * ROWB + c * 16, Beh + (size_t)row * D_DIM + kc + c * 8);
        }
    };

    float acc[4][8][4];
#pragma unroll
    for (int i = 0; i < 4; i++)
#pragma unroll
        for (int j = 0; j < 8; j++)
#pragma unroll
            for (int k = 0; k < 4; k++) acc[i][j][k] = 0.f;

    load_chunk(0, 0); CP_COMMIT();
    load_chunk(1, 1); CP_COMMIT();

    for (int it = 0; it < NCHUNK; it++) {
        if (it + 1 < NCHUNK) { CP_WAIT1(); } else { CP_WAIT0(); }
        __syncthreads();   // chunk `it` resident in slot it%3 for all threads

        if (it + 2 < NCHUNK) {
            load_chunk((it + 2) % NSTAGE, it + 2);   // slot consumed at it-1
            CP_COMMIT();
        }

        uint32_t st   = sb + (it % NSTAGE) * STAGE;
        uint32_t sqh  = st + AQH_OFF;
        uint32_t sql  = st + AQL_OFF;
        uint32_t sbm  = st + B_OFF;
#pragma unroll
        for (int ks = 0; ks < 4; ks++) {
            int k = ks * 16;
            uint32_t aq[4][4], al[4][4];
#pragma unroll
            for (int mi = 0; mi < 4; mi++) {
                int row = warp_m + mi * 16 + (lane & 15);
                int ko  = k + (lane >> 4) * 8;
                ldsm_x4(sqh + row * ROWB + ko * 2, aq[mi][0], aq[mi][1], aq[mi][2], aq[mi][3]);
                ldsm_x4(sql + row * ROWB + ko * 2, al[mi][0], al[mi][1], al[mi][2], al[mi][3]);
            }
            uint32_t b[8][2];
#pragma unroll
            for (int nj = 0; nj < 4; nj++) {
                int n  = warp_n + nj * 16 + (lane & 7) + ((lane >> 4) & 1) * 8;
                int ko = k + ((lane >> 3) & 1) * 8;
                ldsm_x4(sbm + n * ROWB + ko * 2,
                        b[nj * 2][0], b[nj * 2][1], b[nj * 2 + 1][0], b[nj * 2 + 1][1]);
            }
#pragma unroll
            for (int mi = 0; mi < 4; mi++)
#pragma unroll
                for (int nj = 0; nj < 8; nj++) {
                    mma16816(acc[mi][nj], aq[mi], b[nj]);
                    mma16816(acc[mi][nj], al[mi], b[nj]);
                }
        }
        __syncthreads();   // protect slot reuse by the load issued next iter
    }

    // stage vinv for this N tile
    ((float*)smem)[tid] = g_vinv[nblk + tid];
    __syncthreads();
    const float* vin = (const float*)smem;

    // argmax epilogue: rows r0 = warp_m + mi*16 + lane/4 (+8), cols warp_n + nj*8 + 2*(lane&3)
#pragma unroll
    for (int mi = 0; mi < 4; mi++) {
        float bv0 = -1e30f, bv1 = -1e30f;
        int   bj0 = 0,      bj1 = 0;
#pragma unroll
        for (int nj = 0; nj < 8; nj++) {
            int c0 = warp_n + nj * 8 + 2 * (lane & 3);
            float v00 = acc[mi][nj][0] * vin[c0];
            float v01 = acc[mi][nj][1] * vin[c0 + 1];
            float v10 = acc[mi][nj][2] * vin[c0];
            float v11 = acc[mi][nj][3] * vin[c0 + 1];
            if (v00 > bv0) { bv0 = v00; bj0 = c0; }
            if (v01 > bv0) { bv0 = v01; bj0 = c0 + 1; }
            if (v10 > bv1) { bv1 = v10; bj1 = c0; }
            if (v11 > bv1) { bv1 = v11; bj1 = c0 + 1; }
        }
#pragma unroll
        for (int off = 1; off < 4; off <<= 1) {
            float o0 = __shfl_xor_sync(0xffffffffu, bv0, off);
            int   j0 = __shfl_xor_sync(0xffffffffu, bj0, off);
            float o1 = __shfl_xor_sync(0xffffffffu, bv1, off);
            int   j1 = __shfl_xor_sync(0xffffffffu, bj1, off);
            if (o0 > bv0 || (o0 == bv0 && j0 < bj0)) { bv0 = o0; bj0 = j0; }
            if (o1 > bv1 || (o1 == bv1 && j1 < bj1)) { bv1 = o1; bj1 = j1; }
        }
        if ((lane & 3) == 0) {
            int r0 = mblk + warp_m + mi * 16 + (lane >> 2);
            atomicMax(&g_best[r0],     enc_key(bv0, (unsigned)(nblk + bj0)));
            atomicMax(&g_best[r0 + 8], enc_key(bv1, (unsigned)(nblk + bj1)));
        }
    }
}

// ---------------------------------------------------------------------------
// Kernel 4: per-row hinge in exact fp32. One warp per row.
// ---------------------------------------------------------------------------
__global__ void finalize_kernel(const float* __restrict__ emb,
                                const int* __restrict__ target,
                                const int* __restrict__ pad) {
    int r    = blockIdx.x * 8 + (threadIdx.x >> 5);
    int lane = threadIdx.x & 31;
    int t = clamp_idx(target[r]);
    unsigned long long key = g_best[r];
    int jm = clamp_idx((int)(0x7fffffffu - (unsigned)(key & 0xffffffffu)));

    const float* on = g_outn + (size_t)r * D_DIM;
    const float* e1 = emb + (size_t)t  * D_DIM;
    const float* e2 = emb + (size_t)jm * D_DIM;
    float d1 = 0.f, d2 = 0.f;
#pragma unroll
    for (int d = lane; d < D_DIM; d += 32) {
        float o = on[d];
        d1 = fmaf(o, e1[d], d1);
        d2 = fmaf(o, e2[d], d2);
    }
#pragma unroll
    for (int off = 16; off; off >>= 1) {
        d1 += __shfl_xor_sync(0xffffffffu, d1, off);
        d2 += __shfl_xor_sync(0xffffffffu, d2, off);
    }
    if (lane == 0) {
        d1 *= g_vinv[t];
        d2 *= g_vinv[jm];
        float df = fmaxf(GAMMA_F + d2 - d1, 0.f);
        g_diff[r] = (target[r] != *pad) ? df : 0.f;
    }
}

// ---------------------------------------------------------------------------
// Kernel 5: deterministic scalar reduction
// ---------------------------------------------------------------------------
__global__ void reduce_kernel(const int* __restrict__ target,
                              const int* __restrict__ pad,
                              float* __restrict__ out) {
    __shared__ float ssum[1024];
    __shared__ float scnt[1024];
    int t = threadIdx.x;
    int p = *pad;
    float s = 0.f, c = 0.f;
    for (int r = t; r < BS_ROWS; r += 1024) {
        s += g_diff[r];
        c += (target[r] != p) ? 1.f : 0.f;
    }
    ssum[t] = s; scnt[t] = c; __syncthreads();
    for (int off = 512; off; off >>= 1) {
        if (t < off) { ssum[t] += ssum[t + off]; scnt[t] += scnt[t + off]; }
        __syncthreads();
    }
    if (t == 0) out[0] = ssum[0] / scnt[0];
}

// ---------------------------------------------------------------------------
extern "C" void kernel_launch(void* const* d_in, const int* in_sizes, int n_in,
                              void* d_out, int out_size) {
    const float* preds  = (const float*)d_in[0];
    const float* emb    = (const float*)d_in[1];
    const int*   target = (const int*)d_in[2];
    const int*   pad    = (const int*)d_in[3];

    cudaFuncSetAttribute(gemm_mma_kernel, cudaFuncAttributeMaxDynamicSharedMemorySize, SMEMSZ);

    vsplit_kernel<<<V_DIM, 128>>>(emb);
    prep_kernel<<<BS_ROWS, 128>>>(preds, emb, target);
    dim3 grid(BS_ROWS / MT, V_DIM / NT);   // (16, 125)
    gemm_mma_kernel<<<grid, 256, SMEMSZ>>>();
    finalize_kernel<<<BS_ROWS / 8, 256>>>(emb, target, pad);
    reduce_kernel<<<1, 1024>>>(target, pad, (float*)d_out);
}

// round 6
// speedup vs baseline: 5.6594x; 1.5364x over previous
#include <cuda_runtime.h>
#include <cuda_fp16.h>
#include <math.h>
#include <stdint.h>

// Problem constants
#define D_DIM   512
#define V_DIM   32000
#define BS_ROWS 2048
#define GAMMA_F 0.5f
#define EPS_F   1e-12f

// GEMM tiling
#define MT 128
#define NT 256
#define KC 64               // fp16 K per chunk (128 B rows)
#define NCHUNK 8            // 512 / 64
#define NSTAGE 3

// SMEM: rows padded to 72 halves (144 B) for conflict-free ldmatrix
#define ROWB   144
#define A_OFF  0
#define B_OFF  (MT * ROWB)               // 18432
#define STAGE  ((MT + NT) * ROWB)        // 55296
#define SMEMSZ (NSTAGE * STAGE)          // 165888

// ---------------------------------------------------------------------------
// Static scratch
// ---------------------------------------------------------------------------
__device__ __half g_qh[BS_ROWS * D_DIM];
__device__ __half g_eh[(size_t)V_DIM * D_DIM];
__device__ float              g_vinv[V_DIM];
__device__ float              g_outn[BS_ROWS * D_DIM];
__device__ unsigned long long g_best[BS_ROWS];
__device__ float              g_diff[BS_ROWS];

// ---------------------------------------------------------------------------
// helpers
// ---------------------------------------------------------------------------
__device__ __forceinline__ uint32_t smem_u32(const void* p) {
    uint32_t a;
    asm("{ .reg .u64 t; cvta.to.shared.u64 t, %1; cvt.u32.u64 %0, t; }" : "=r"(a) : "l"(p));
    return a;
}
__device__ __forceinline__ void cp16(uint32_t dst, const void* src) {
    asm volatile("cp.async.cg.shared.global [%0], [%1], 16;" :: "r"(dst), "l"(src));
}
#define CP_COMMIT() asm volatile("cp.async.commit_group;" ::: "memory")
#define CP_WAIT1()  asm volatile("cp.async.wait_group 1;" ::: "memory")
#define CP_WAIT0()  asm volatile("cp.async.wait_group 0;" ::: "memory")

__device__ __forceinline__ void ldsm_x4(uint32_t addr, uint32_t& r0, uint32_t& r1,
                                        uint32_t& r2, uint32_t& r3) {
    asm volatile("ldmatrix.sync.aligned.m8n8.x4.shared.b16 {%0,%1,%2,%3}, [%4];"
                 : "=r"(r0), "=r"(r1), "=r"(r2), "=r"(r3) : "r"(addr));
}
__device__ __forceinline__ void mma16816(float* c, const uint32_t* a, const uint32_t* b) {
    asm volatile(
        "mma.sync.aligned.m16n8k16.row.col.f32.f16.f16.f32 "
        "{%0,%1,%2,%3}, {%4,%5,%6,%7}, {%8,%9}, {%0,%1,%2,%3};"
        : "+f"(c[0]), "+f"(c[1]), "+f"(c[2]), "+f"(c[3])
        : "r"(a[0]), "r"(a[1]), "r"(a[2]), "r"(a[3]), "r"(b[0]), "r"(b[1]));
}

// Monotone (score, idx) packing; bigger score wins, tie -> smaller index
__device__ __forceinline__ unsigned long long enc_key(float v, unsigned idx) {
    unsigned u = __float_as_uint(v);
    u = (u & 0x80000000u) ? ~u : (u | 0x80000000u);
    return ((unsigned long long)u << 32) | (unsigned long long)(0x7fffffffu - idx);
}
__device__ __forceinline__ int clamp_idx(int t) {
    t = t < 0 ? 0 : t;
    return t >= V_DIM ? V_DIM - 1 : t;
}

// ---------------------------------------------------------------------------
// Kernel 1: vocab pass — vinv + fp16 copy. One block(128) per row.
// ---------------------------------------------------------------------------
__global__ void vsplit_kernel(const float* __restrict__ emb) {
    __shared__ float red[128];
    int r = blockIdx.x;
    const float4* row = (const float4*)(emb + (size_t)r * D_DIM);
    float4 v = row[threadIdx.x];
    float ss = v.x * v.x + v.y * v.y + v.z * v.z + v.w * v.w;
    red[threadIdx.x] = ss; __syncthreads();
    for (int off = 64; off; off >>= 1) {
        if (threadIdx.x < off) red[threadIdx.x] += red[threadIdx.x + off];
        __syncthreads();
    }
    if (threadIdx.x == 0) g_vinv[r] = 1.f / fmaxf(sqrtf(red[0]), EPS_F);

    size_t base = (size_t)r * D_DIM + threadIdx.x * 4;
    *(__half2*)(g_eh + base)     = __halves2half2(__float2half_rn(v.x), __float2half_rn(v.y));
    *(__half2*)(g_eh + base + 2) = __halves2half2(__float2half_rn(v.z), __float2half_rn(v.w));
}

// ---------------------------------------------------------------------------
// Kernel 2: out_norm + q = out_norm - emb[target] in fp16.
// One block(128) per row. Resets g_best.
// ---------------------------------------------------------------------------
__global__ void prep_kernel(const float* __restrict__ preds,
                            const float* __restrict__ emb,
                            const int* __restrict__ target) {
    __shared__ float red[128];
    int r = blockIdx.x;
    int b = r >> 9, s = r & 511;
    const float* col = preds + ((size_t)b * D_DIM * 512 + s);
    float v[4]; float ss = 0.f;
#pragma unroll
    for (int i = 0; i < 4; i++) {
        int d = threadIdx.x + i * 128;
        v[i] = col[(size_t)d * 512];
        ss = fmaf(v[i], v[i], ss);
    }
    red[threadIdx.x] = ss; __syncthreads();
    for (int off = 64; off; off >>= 1) {
        if (threadIdx.x < off) red[threadIdx.x] += red[threadIdx.x + off];
        __syncthreads();
    }
    float inv = 1.f / fmaxf(sqrtf(red[0]), EPS_F);
    int t = clamp_idx(target[r]);
    const float* erow = emb + (size_t)t * D_DIM;
#pragma unroll
    for (int i = 0; i < 4; i++) {
        int d = threadIdx.x + i * 128;
        float on = v[i] * inv;
        g_outn[(size_t)r * D_DIM + d] = on;
        g_qh[(size_t)r * D_DIM + d] = __float2half_rn(on - erow[d]);
    }
    if (threadIdx.x == 0) g_best[r] = 0ull;
}

// ---------------------------------------------------------------------------
// Kernel 3: fp16 mma.sync GEMM (single pass), 3-stage cp.async pipeline,
// fused vinv-scale + argmax. CTA 128x256, 8 warps (warp tile 64x64).
// ---------------------------------------------------------------------------
__global__ void __launch_bounds__(256, 1) gemm_mma_kernel() {
    extern __shared__ char smem[];
    const uint32_t sb = smem_u32(smem);
    const int tid  = threadIdx.x;
    const int wid  = tid >> 5;
    const int lane = tid & 31;
    const int mblk = blockIdx.x * MT;
    const int nblk = blockIdx.y * NT;
    const int warp_m = (wid & 1) * 64;
    const int warp_n = (wid >> 1) * 64;

    const __half* Aqh = g_qh + (size_t)mblk * D_DIM;
    const __half* Beh = g_eh + (size_t)nblk * D_DIM;

    auto load_chunk = [&](int slot, int ch) {
        int kc = ch * KC;
        uint32_t st = sb + slot * STAGE;
        // A: 128 rows * 8 segs(16B) = 1024 -> 4 per thread
#pragma unroll
        for (int i = 0; i < 4; i++) {
            int s = tid + i * 256;
            int row = s >> 3, c = s & 7;
            cp16(st + A_OFF + row * ROWB + c * 16, Aqh + (size_t)row * D_DIM + kc + c * 8);
        }
        // B: 256 rows * 8 segs = 2048 -> 8 per thread
#pragma unroll
        for (int i = 0; i < 8; i++) {
            int s = tid + i * 256;
            int row = s >> 3, c = s & 7;
            cp16(st + B_OFF + row * ROWB + c * 16, Beh + (size_t)row * D_DIM + kc + c * 8);
        }
    };

    float acc[4][8][4];
#pragma unroll
    for (int i = 0; i < 4; i++)
#pragma unroll
        for (int j = 0; j < 8; j++)
#pragma unroll
            for (int k = 0; k < 4; k++) acc[i][j][k] = 0.f;

    load_chunk(0, 0); CP_COMMIT();
    load_chunk(1, 1); CP_COMMIT();

    for (int it = 0; it < NCHUNK; it++) {
        if (it + 1 < NCHUNK) { CP_WAIT1(); } else { CP_WAIT0(); }
        __syncthreads();   // chunk `it` resident in slot it%3 for all threads

        if (it + 2 < NCHUNK) {
            load_chunk((it + 2) % NSTAGE, it + 2);   // slot consumed at it-1
            CP_COMMIT();
        }

        uint32_t st  = sb + (it % NSTAGE) * STAGE;
        uint32_t sa  = st + A_OFF;
        uint32_t sbm = st + B_OFF;
#pragma unroll
        for (int ks = 0; ks < 4; ks++) {
            int k = ks * 16;
            uint32_t a[4][4];
#pragma unroll
            for (int mi = 0; mi < 4; mi++) {
                int row = warp_m + mi * 16 + (lane & 15);
                int ko  = k + (lane >> 4) * 8;
                ldsm_x4(sa + row * ROWB + ko * 2, a[mi][0], a[mi][1], a[mi][2], a[mi][3]);
            }
            uint32_t b[8][2];
#pragma unroll
            for (int nj = 0; nj < 4; nj++) {
                int n  = warp_n + nj * 16 + (lane & 7) + ((lane >> 4) & 1) * 8;
                int ko = k + ((lane >> 3) & 1) * 8;
                ldsm_x4(sbm + n * ROWB + ko * 2,
                        b[nj * 2][0], b[nj * 2][1], b[nj * 2 + 1][0], b[nj * 2 + 1][1]);
            }
#pragma unroll
            for (int mi = 0; mi < 4; mi++)
#pragma unroll
                for (int nj = 0; nj < 8; nj++)
                    mma16816(acc[mi][nj], a[mi], b[nj]);
        }
        __syncthreads();   // protect slot reuse by the load issued next iter
    }

    // stage vinv for this N tile
    ((float*)smem)[tid] = g_vinv[nblk + tid];
    __syncthreads();
    const float* vin = (const float*)smem;

    // argmax epilogue: rows r0 = warp_m + mi*16 + lane/4 (+8), cols warp_n + nj*8 + 2*(lane&3)
#pragma unroll
    for (int mi = 0; mi < 4; mi++) {
        float bv0 = -1e30f, bv1 = -1e30f;
        int   bj0 = 0,      bj1 = 0;
#pragma unroll
        for (int nj = 0; nj < 8; nj++) {
            int c0 = warp_n + nj * 8 + 2 * (lane & 3);
            float v00 = acc[mi][nj][0] * vin[c0];
            float v01 = acc[mi][nj][1] * vin[c0 + 1];
            float v10 = acc[mi][nj][2] * vin[c0];
            float v11 = acc[mi][nj][3] * vin[c0 + 1];
            if (v00 > bv0) { bv0 = v00; bj0 = c0; }
            if (v01 > bv0) { bv0 = v01; bj0 = c0 + 1; }
            if (v10 > bv1) { bv1 = v10; bj1 = c0; }
            if (v11 > bv1) { bv1 = v11; bj1 = c0 + 1; }
        }
#pragma unroll
        for (int off = 1; off < 4; off <<= 1) {
            float o0 = __shfl_xor_sync(0xffffffffu, bv0, off);
            int   j0 = __shfl_xor_sync(0xffffffffu, bj0, off);
            float o1 = __shfl_xor_sync(0xffffffffu, bv1, off);
            int   j1 = __shfl_xor_sync(0xffffffffu, bj1, off);
            if (o0 > bv0 || (o0 == bv0 && j0 < bj0)) { bv0 = o0; bj0 = j0; }
            if (o1 > bv1 || (o1 == bv1 && j1 < bj1)) { bv1 = o1; bj1 = j1; }
        }
        if ((lane & 3) == 0) {
            int r0 = mblk + warp_m + mi * 16 + (lane >> 2);
            atomicMax(&g_best[r0],     enc_key(bv0, (unsigned)(nblk + bj0)));
            atomicMax(&g_best[r0 + 8], enc_key(bv1, (unsigned)(nblk + bj1)));
        }
    }
}

// ---------------------------------------------------------------------------
// Kernel 4: per-row hinge in exact fp32. One warp per row.
// ---------------------------------------------------------------------------
__global__ void finalize_kernel(const float* __restrict__ emb,
                                const int* __restrict__ target,
                                const int* __restrict__ pad) {
    int r    = blockIdx.x * 8 + (threadIdx.x >> 5);
    int lane = threadIdx.x & 31;
    int t = clamp_idx(target[r]);
    unsigned long long key = g_best[r];
    int jm = clamp_idx((int)(0x7fffffffu - (unsigned)(key & 0xffffffffu)));

    const float* on = g_outn + (size_t)r * D_DIM;
    const float* e1 = emb + (size_t)t  * D_DIM;
    const float* e2 = emb + (size_t)jm * D_DIM;
    float d1 = 0.f, d2 = 0.f;
#pragma unroll
    for (int d = lane; d < D_DIM; d += 32) {
        float o = on[d];
        d1 = fmaf(o, e1[d], d1);
        d2 = fmaf(o, e2[d], d2);
    }
#pragma unroll
    for (int off = 16; off; off >>= 1) {
        d1 += __shfl_xor_sync(0xffffffffu, d1, off);
        d2 += __shfl_xor_sync(0xffffffffu, d2, off);
    }
    if (lane == 0) {
        d1 *= g_vinv[t];
        d2 *= g_vinv[jm];
        float df = fmaxf(GAMMA_F + d2 - d1, 0.f);
        g_diff[r] = (target[r] != *pad) ? df : 0.f;
    }
}

// ---------------------------------------------------------------------------
// Kernel 5: deterministic scalar reduction
// ---------------------------------------------------------------------------
__global__ void reduce_kernel(const int* __restrict__ target,
                              const int* __restrict__ pad,
                              float* __restrict__ out) {
    __shared__ float ssum[1024];
    __shared__ float scnt[1024];
    int t = threadIdx.x;
    int p = *pad;
    float s = 0.f, c = 0.f;
    for (int r = t; r < BS_ROWS; r += 1024) {
        s += g_diff[r];
        c += (target[r] != p) ? 1.f : 0.f;
    }
    ssum[t] = s; scnt[t] = c; __syncthreads();
    for (int off = 512; off; off >>= 1) {
        if (t < off) { ssum[t] += ssum[t + off]; scnt[t] += scnt[t + off]; }
        __syncthreads();
    }
    if (t == 0) out[0] = ssum[0] / scnt[0];
}

// ---------------------------------------------------------------------------
extern "C" void kernel_launch(void* const* d_in, const int* in_sizes, int n_in,
                              void* d_out, int out_size) {
    const float* preds  = (const float*)d_in[0];
    const float* emb    = (const float*)d_in[1];
    const int*   target = (const int*)d_in[2];
    const int*   pad    = (const int*)d_in[3];

    cudaFuncSetAttribute(gemm_mma_kernel, cudaFuncAttributeMaxDynamicSharedMemorySize, SMEMSZ);

    vsplit_kernel<<<V_DIM, 128>>>(emb);
    prep_kernel<<<BS_ROWS, 128>>>(preds, emb, target);
    dim3 grid(BS_ROWS / MT, V_DIM / NT);   // (16, 125)
    gemm_mma_kernel<<<grid, 256, SMEMSZ>>>();
    finalize_kernel<<<BS_ROWS / 8, 256>>>(emb, target, pad);
    reduce_kernel<<<1, 1024>>>(target, pad, (float*)d_out);
}

// round 7
// speedup vs baseline: 6.4606x; 1.1416x over previous
#include <cuda_runtime.h>
#include <cuda_fp16.h>
#include <math.h>
#include <stdint.h>

// Problem constants
#define D_DIM   512
#define V_DIM   32000
#define BS_ROWS 2048
#define GAMMA_F 0.5f
#define EPS_F   1e-12f

// GEMM tiling: CTA 128x128, 8 warps, warp tile 32x64, 2 CTAs/SM
#define MT 128
#define NT 128
#define KC 64               // fp16 K per chunk (128 B rows)
#define NCHUNK 8            // 512 / 64
#define NSTAGE 3

// SMEM: rows padded to 72 halves (144 B) for conflict-free ldmatrix
#define ROWB   144
#define A_OFF  0
#define B_OFF  (MT * ROWB)               // 18432
#define STAGE  ((MT + NT) * ROWB)        // 36864
#define SMEMSZ (NSTAGE * STAGE)          // 110592

// ---------------------------------------------------------------------------
// Static scratch
// ---------------------------------------------------------------------------
__device__ __half g_qh[BS_ROWS * D_DIM];
__device__ __half g_eh[(size_t)V_DIM * D_DIM];
__device__ float              g_vinv[V_DIM];
__device__ float              g_outn[BS_ROWS * D_DIM];
__device__ unsigned long long g_best[BS_ROWS];
__device__ float              g_diff[BS_ROWS];

// ---------------------------------------------------------------------------
// helpers
// ---------------------------------------------------------------------------
__device__ __forceinline__ uint32_t smem_u32(const void* p) {
    uint32_t a;
    asm("{ .reg .u64 t; cvta.to.shared.u64 t, %1; cvt.u32.u64 %0, t; }" : "=r"(a) : "l"(p));
    return a;
}
__device__ __forceinline__ void cp16(uint32_t dst, const void* src) {
    asm volatile("cp.async.cg.shared.global [%0], [%1], 16;" :: "r"(dst), "l"(src));
}
#define CP_COMMIT() asm volatile("cp.async.commit_group;" ::: "memory")
#define CP_WAIT1()  asm volatile("cp.async.wait_group 1;" ::: "memory")
#define CP_WAIT0()  asm volatile("cp.async.wait_group 0;" ::: "memory")

__device__ __forceinline__ void ldsm_x4(uint32_t addr, uint32_t& r0, uint32_t& r1,
                                        uint32_t& r2, uint32_t& r3) {
    asm volatile("ldmatrix.sync.aligned.m8n8.x4.shared.b16 {%0,%1,%2,%3}, [%4];"
                 : "=r"(r0), "=r"(r1), "=r"(r2), "=r"(r3) : "r"(addr));
}
__device__ __forceinline__ void mma16816(float* c, const uint32_t* a, const uint32_t* b) {
    asm volatile(
        "mma.sync.aligned.m16n8k16.row.col.f32.f16.f16.f32 "
        "{%0,%1,%2,%3}, {%4,%5,%6,%7}, {%8,%9}, {%0,%1,%2,%3};"
        : "+f"(c[0]), "+f"(c[1]), "+f"(c[2]), "+f"(c[3])
        : "r"(a[0]), "r"(a[1]), "r"(a[2]), "r"(a[3]), "r"(b[0]), "r"(b[1]));
}

// Monotone (score, idx) packing; bigger score wins, tie -> smaller index
__device__ __forceinline__ unsigned long long enc_key(float v, unsigned idx) {
    unsigned u = __float_as_uint(v);
    u = (u & 0x80000000u) ? ~u : (u | 0x80000000u);
    return ((unsigned long long)u << 32) | (unsigned long long)(0x7fffffffu - idx);
}
__device__ __forceinline__ int clamp_idx(int t) {
    t = t < 0 ? 0 : t;
    return t >= V_DIM ? V_DIM - 1 : t;
}

// ---------------------------------------------------------------------------
// Kernel 1: vocab pass — vinv + fp16 copy. One block(128) per row.
// ---------------------------------------------------------------------------
__global__ void vsplit_kernel(const float* __restrict__ emb) {
    __shared__ float red[128];
    int r = blockIdx.x;
    const float4* row = (const float4*)(emb + (size_t)r * D_DIM);
    float4 v = row[threadIdx.x];
    float ss = v.x * v.x + v.y * v.y + v.z * v.z + v.w * v.w;
    red[threadIdx.x] = ss; __syncthreads();
    for (int off = 64; off; off >>= 1) {
        if (threadIdx.x < off) red[threadIdx.x] += red[threadIdx.x + off];
        __syncthreads();
    }
    if (threadIdx.x == 0) g_vinv[r] = 1.f / fmaxf(sqrtf(red[0]), EPS_F);

    size_t base = (size_t)r * D_DIM + threadIdx.x * 4;
    *(__half2*)(g_eh + base)     = __halves2half2(__float2half_rn(v.x), __float2half_rn(v.y));
    *(__half2*)(g_eh + base + 2) = __halves2half2(__float2half_rn(v.z), __float2half_rn(v.w));
}

// ---------------------------------------------------------------------------
// Kernel 2: out_norm + q = out_norm - emb[target] in fp16.
// One block(128) per row. Resets g_best.
// ---------------------------------------------------------------------------
__global__ void prep_kernel(const float* __restrict__ preds,
                            const float* __restrict__ emb,
                            const int* __restrict__ target) {
    __shared__ float red[128];
    int r = blockIdx.x;
    int b = r >> 9, s = r & 511;
    const float* col = preds + ((size_t)b * D_DIM * 512 + s);
    float v[4]; float ss = 0.f;
#pragma unroll
    for (int i = 0; i < 4; i++) {
        int d = threadIdx.x + i * 128;
        v[i] = col[(size_t)d * 512];
        ss = fmaf(v[i], v[i], ss);
    }
    red[threadIdx.x] = ss; __syncthreads();
    for (int off = 64; off; off >>= 1) {
        if (threadIdx.x < off) red[threadIdx.x] += red[threadIdx.x + off];
        __syncthreads();
    }
    float inv = 1.f / fmaxf(sqrtf(red[0]), EPS_F);
    int t = clamp_idx(target[r]);
    const float* erow = emb + (size_t)t * D_DIM;
#pragma unroll
    for (int i = 0; i < 4; i++) {
        int d = threadIdx.x + i * 128;
        float on = v[i] * inv;
        g_outn[(size_t)r * D_DIM + d] = on;
        g_qh[(size_t)r * D_DIM + d] = __float2half_rn(on - erow[d]);
    }
    if (threadIdx.x == 0) g_best[r] = 0ull;
}

// ---------------------------------------------------------------------------
// Kernel 3: fp16 mma.sync GEMM, 3-stage cp.async, 2 CTAs/SM,
// fused vinv-scale + argmax. CTA 128x128, 8 warps (warp tile 32x64).
// ---------------------------------------------------------------------------
__global__ void __launch_bounds__(256, 2) gemm_mma_kernel() {
    extern __shared__ char smem[];
    const uint32_t sb = smem_u32(smem);
    const int tid  = threadIdx.x;
    const int wid  = tid >> 5;
    const int lane = tid & 31;
    const int mblk = blockIdx.x * MT;
    const int nblk = blockIdx.y * NT;
    const int warp_m = (wid & 3) * 32;      // 4 warps along M
    const int warp_n = (wid >> 2) * 64;     // 2 warps along N

    const __half* Aqh = g_qh + (size_t)mblk * D_DIM;
    const __half* Beh = g_eh + (size_t)nblk * D_DIM;

    auto load_chunk = [&](int slot, int ch) {
        int kc = ch * KC;
        uint32_t st = sb + slot * STAGE;
        // A: 128 rows * 8 segs(16B) = 1024 -> 4 per thread; B same
#pragma unroll
        for (int i = 0; i < 4; i++) {
            int s = tid + i * 256;
            int row = s >> 3, c = s & 7;
            cp16(st + A_OFF + row * ROWB + c * 16, Aqh + (size_t)row * D_DIM + kc + c * 8);
            cp16(st + B_OFF + row * ROWB + c * 16, Beh + (size_t)row * D_DIM + kc + c * 8);
        }
    };

    float acc[2][8][4];
#pragma unroll
    for (int i = 0; i < 2; i++)
#pragma unroll
        for (int j = 0; j < 8; j++)
#pragma unroll
            for (int k = 0; k < 4; k++) acc[i][j][k] = 0.f;

    load_chunk(0, 0); CP_COMMIT();
    load_chunk(1, 1); CP_COMMIT();

    for (int it = 0; it < NCHUNK; it++) {
        if (it + 1 < NCHUNK) { CP_WAIT1(); } else { CP_WAIT0(); }
        __syncthreads();   // chunk `it` resident in slot it%3 for all threads

        if (it + 2 < NCHUNK) {
            load_chunk((it + 2) % NSTAGE, it + 2);   // slot consumed at it-1
            CP_COMMIT();
        }

        uint32_t st  = sb + (it % NSTAGE) * STAGE;
        uint32_t sa  = st + A_OFF;
        uint32_t sbm = st + B_OFF;
#pragma unroll
        for (int ks = 0; ks < 4; ks++) {
            int k = ks * 16;
            uint32_t a[2][4];
#pragma unroll
            for (int mi = 0; mi < 2; mi++) {
                int row = warp_m + mi * 16 + (lane & 15);
                int ko  = k + (lane >> 4) * 8;
                ldsm_x4(sa + row * ROWB + ko * 2, a[mi][0], a[mi][1], a[mi][2], a[mi][3]);
            }
            uint32_t b[8][2];
#pragma unroll
            for (int nj = 0; nj < 4; nj++) {
                int n  = warp_n + nj * 16 + (lane & 7) + ((lane >> 4) & 1) * 8;
                int ko = k + ((lane >> 3) & 1) * 8;
                ldsm_x4(sbm + n * ROWB + ko * 2,
                        b[nj * 2][0], b[nj * 2][1], b[nj * 2 + 1][0], b[nj * 2 + 1][1]);
            }
#pragma unroll
            for (int mi = 0; mi < 2; mi++)
#pragma unroll
                for (int nj = 0; nj < 8; nj++)
                    mma16816(acc[mi][nj], a[mi], b[nj]);
        }
        __syncthreads();   // protect slot reuse by the load issued next iter
    }

    // stage vinv for this N tile (128 floats)
    if (tid < NT) ((float*)smem)[tid] = g_vinv[nblk + tid];
    __syncthreads();
    const float* vin = (const float*)smem;

    // argmax epilogue: rows r0 = warp_m + mi*16 + lane/4 (+8), cols warp_n + nj*8 + 2*(lane&3)
#pragma unroll
    for (int mi = 0; mi < 2; mi++) {
        float bv0 = -1e30f, bv1 = -1e30f;
        int   bj0 = 0,      bj1 = 0;
#pragma unroll
        for (int nj = 0; nj < 8; nj++) {
            int c0 = warp_n + nj * 8 + 2 * (lane & 3);
            float v00 = acc[mi][nj][0] * vin[c0];
            float v01 = acc[mi][nj][1] * vin[c0 + 1];
            float v10 = acc[mi][nj][2] * vin[c0];
            float v11 = acc[mi][nj][3] * vin[c0 + 1];
            if (v00 > bv0) { bv0 = v00; bj0 = c0; }
            if (v01 > bv0) { bv0 = v01; bj0 = c0 + 1; }
            if (v10 > bv1) { bv1 = v10; bj1 = c0; }
            if (v11 > bv1) { bv1 = v11; bj1 = c0 + 1; }
        }
#pragma unroll
        for (int off = 1; off < 4; off <<= 1) {
            float o0 = __shfl_xor_sync(0xffffffffu, bv0, off);
            int   j0 = __shfl_xor_sync(0xffffffffu, bj0, off);
            float o1 = __shfl_xor_sync(0xffffffffu, bv1, off);
            int   j1 = __shfl_xor_sync(0xffffffffu, bj1, off);
            if (o0 > bv0 || (o0 == bv0 && j0 < bj0)) { bv0 = o0; bj0 = j0; }
            if (o1 > bv1 || (o1 == bv1 && j1 < bj1)) { bv1 = o1; bj1 = j1; }
        }
        if ((lane & 3) == 0) {
            int r0 = mblk + warp_m + mi * 16 + (lane >> 2);
            atomicMax(&g_best[r0],     enc_key(bv0, (unsigned)(nblk + bj0)));
            atomicMax(&g_best[r0 + 8], enc_key(bv1, (unsigned)(nblk + bj1)));
        }
    }
}

// ---------------------------------------------------------------------------
// Kernel 4: per-row hinge in exact fp32. One warp per row.
// ---------------------------------------------------------------------------
__global__ void finalize_kernel(const float* __restrict__ emb,
                                const int* __restrict__ target,
                                const int* __restrict__ pad) {
    int r    = blockIdx.x * 8 + (threadIdx.x >> 5);
    int lane = threadIdx.x & 31;
    int t = clamp_idx(target[r]);
    unsigned long long key = g_best[r];
    int jm = clamp_idx((int)(0x7fffffffu - (unsigned)(key & 0xffffffffu)));

    const float* on = g_outn + (size_t)r * D_DIM;
    const float* e1 = emb + (size_t)t  * D_DIM;
    const float* e2 = emb + (size_t)jm * D_DIM;
    float d1 = 0.f, d2 = 0.f;
#pragma unroll
    for (int d = lane; d < D_DIM; d += 32) {
        float o = on[d];
        d1 = fmaf(o, e1[d], d1);
        d2 = fmaf(o, e2[d], d2);
    }
#pragma unroll
    for (int off = 16; off; off >>= 1) {
        d1 += __shfl_xor_sync(0xffffffffu, d1, off);
        d2 += __shfl_xor_sync(0xffffffffu, d2, off);
    }
    if (lane == 0) {
        d1 *= g_vinv[t];
        d2 *= g_vinv[jm];
        float df = fmaxf(GAMMA_F + d2 - d1, 0.f);
        g_diff[r] = (target[r] != *pad) ? df : 0.f;
    }
}

// ---------------------------------------------------------------------------
// Kernel 5: deterministic scalar reduction
// ---------------------------------------------------------------------------
__global__ void reduce_kernel(const int* __restrict__ target,
                              const int* __restrict__ pad,
                              float* __restrict__ out) {
    __shared__ float ssum[1024];
    __shared__ float scnt[1024];
    int t = threadIdx.x;
    int p = *pad;
    float s = 0.f, c = 0.f;
    for (int r = t; r < BS_ROWS; r += 1024) {
        s += g_diff[r];
        c += (target[r] != p) ? 1.f : 0.f;
    }
    ssum[t] = s; scnt[t] = c; __syncthreads();
    for (int off = 512; off; off >>= 1) {
        if (t < off) { ssum[t] += ssum[t + off]; scnt[t] += scnt[t + off]; }
        __syncthreads();
    }
    if (t == 0) out[0] = ssum[0] / scnt[0];
}

// ---------------------------------------------------------------------------
extern "C" void kernel_launch(void* const* d_in, const int* in_sizes, int n_in,
                              void* d_out, int out_size) {
    const float* preds  = (const float*)d_in[0];
    const float* emb    = (const float*)d_in[1];
    const int*   target = (const int*)d_in[2];
    const int*   pad    = (const int*)d_in[3];

    cudaFuncSetAttribute(gemm_mma_kernel, cudaFuncAttributeMaxDynamicSharedMemorySize, SMEMSZ);

    vsplit_kernel<<<V_DIM, 128>>>(emb);
    prep_kernel<<<BS_ROWS, 128>>>(preds, emb, target);
    dim3 grid(BS_ROWS / MT, V_DIM / NT);   // (16, 250)
    gemm_mma_kernel<<<grid, 256, SMEMSZ>>>();
    finalize_kernel<<<BS_ROWS / 8, 256>>>(emb, target, pad);
    reduce_kernel<<<1, 1024>>>(target, pad, (float*)d_out);
}

// round 8
// speedup vs baseline: 7.1721x; 1.1101x over previous
#include <cuda_runtime.h>
#include <cuda_fp16.h>
#include <math.h>
#include <stdint.h>

// Problem constants
#define D_DIM   512
#define V_DIM   32000
#define BS_ROWS 2048
#define GAMMA_F 0.5f
#define EPS_F   1e-12f

// GEMM tiling: CTA 128x160, 8 warps (warp tile 32x80), 2 CTAs/SM
#define MT 128
#define NT 160
#define KC 64               // fp16 K per chunk (128 B rows)
#define NCHUNK 8            // 512 / 64
#define NSTAGE 3

// SMEM: 128B rows with XOR swizzle (chunk ^= row&7) -> conflict-free ldmatrix
#define ROWB   128
#define A_OFF  0
#define B_OFF  (MT * ROWB)               // 16384
#define STAGE  ((MT + NT) * ROWB)        // 36864
#define SMEMSZ (NSTAGE * STAGE)          // 110592

// ---------------------------------------------------------------------------
// Static scratch
// ---------------------------------------------------------------------------
__device__ __half g_qh[BS_ROWS * D_DIM];
__device__ __half g_eh[(size_t)V_DIM * D_DIM];
__device__ float              g_vinv[V_DIM];
__device__ float              g_outn[BS_ROWS * D_DIM];
__device__ unsigned long long g_best[BS_ROWS];
__device__ float              g_diff[BS_ROWS];

// ---------------------------------------------------------------------------
// helpers
// ---------------------------------------------------------------------------
__device__ __forceinline__ uint32_t smem_u32(const void* p) {
    uint32_t a;
    asm("{ .reg .u64 t; cvta.to.shared.u64 t, %1; cvt.u32.u64 %0, t; }" : "=r"(a) : "l"(p));
    return a;
}
__device__ __forceinline__ void cp16(uint32_t dst, const void* src) {
    asm volatile("cp.async.cg.shared.global [%0], [%1], 16;" :: "r"(dst), "l"(src));
}
#define CP_COMMIT() asm volatile("cp.async.commit_group;" ::: "memory")
#define CP_WAIT1()  asm volatile("cp.async.wait_group 1;" ::: "memory")
#define CP_WAIT0()  asm volatile("cp.async.wait_group 0;" ::: "memory")

__device__ __forceinline__ void ldsm_x4(uint32_t addr, uint32_t& r0, uint32_t& r1,
                                        uint32_t& r2, uint32_t& r3) {
    asm volatile("ldmatrix.sync.aligned.m8n8.x4.shared.b16 {%0,%1,%2,%3}, [%4];"
                 : "=r"(r0), "=r"(r1), "=r"(r2), "=r"(r3) : "r"(addr));
}
__device__ __forceinline__ void mma16816(float* c, const uint32_t* a, const uint32_t* b) {
    asm volatile(
        "mma.sync.aligned.m16n8k16.row.col.f32.f16.f16.f32 "
        "{%0,%1,%2,%3}, {%4,%5,%6,%7}, {%8,%9}, {%0,%1,%2,%3};"
        : "+f"(c[0]), "+f"(c[1]), "+f"(c[2]), "+f"(c[3])
        : "r"(a[0]), "r"(a[1]), "r"(a[2]), "r"(a[3]), "r"(b[0]), "r"(b[1]));
}

// XOR swizzle: 16B chunk index within a 128B row, xored with row&7
__device__ __forceinline__ uint32_t swz(uint32_t row, uint32_t chunk) {
    return row * ROWB + ((chunk ^ (row & 7u)) << 4);
}

// Monotone (score, idx) packing; bigger score wins, tie -> smaller index
__device__ __forceinline__ unsigned long long enc_key(float v, unsigned idx) {
    unsigned u = __float_as_uint(v);
    u = (u & 0x80000000u) ? ~u : (u | 0x80000000u);
    return ((unsigned long long)u << 32) | (unsigned long long)(0x7fffffffu - idx);
}
__device__ __forceinline__ int clamp_idx(int t) {
    t = t < 0 ? 0 : t;
    return t >= V_DIM ? V_DIM - 1 : t;
}

// ---------------------------------------------------------------------------
// Kernel 1: vocab pass — vinv + fp16 copy. One block(128) per row.
// ---------------------------------------------------------------------------
__global__ void vsplit_kernel(const float* __restrict__ emb) {
    __shared__ float red[128];
    int r = blockIdx.x;
    const float4* row = (const float4*)(emb + (size_t)r * D_DIM);
    float4 v = row[threadIdx.x];
    float ss = v.x * v.x + v.y * v.y + v.z * v.z + v.w * v.w;
    red[threadIdx.x] = ss; __syncthreads();
    for (int off = 64; off; off >>= 1) {
        if (threadIdx.x < off) red[threadIdx.x] += red[threadIdx.x + off];
        __syncthreads();
    }
    if (threadIdx.x == 0) g_vinv[r] = 1.f / fmaxf(sqrtf(red[0]), EPS_F);

    size_t base = (size_t)r * D_DIM + threadIdx.x * 4;
    *(__half2*)(g_eh + base)     = __halves2half2(__float2half_rn(v.x), __float2half_rn(v.y));
    *(__half2*)(g_eh + base + 2) = __halves2half2(__float2half_rn(v.z), __float2half_rn(v.w));
}

// ---------------------------------------------------------------------------
// Kernel 2: out_norm + q = out_norm - emb[target] in fp16.
// One block(128) per row. Resets g_best.
// ---------------------------------------------------------------------------
__global__ void prep_kernel(const float* __restrict__ preds,
                            const float* __restrict__ emb,
                            const int* __restrict__ target) {
    __shared__ float red[128];
    int r = blockIdx.x;
    int b = r >> 9, s = r & 511;
    const float* col = preds + ((size_t)b * D_DIM * 512 + s);
    float v[4]; float ss = 0.f;
#pragma unroll
    for (int i = 0; i < 4; i++) {
        int d = threadIdx.x + i * 128;
        v[i] = col[(size_t)d * 512];
        ss = fmaf(v[i], v[i], ss);
    }
    red[threadIdx.x] = ss; __syncthreads();
    for (int off = 64; off; off >>= 1) {
        if (threadIdx.x < off) red[threadIdx.x] += red[threadIdx.x + off];
        __syncthreads();
    }
    float inv = 1.f / fmaxf(sqrtf(red[0]), EPS_F);
    int t = clamp_idx(target[r]);
    const float* erow = emb + (size_t)t * D_DIM;
#pragma unroll
    for (int i = 0; i < 4; i++) {
        int d = threadIdx.x + i * 128;
        float on = v[i] * inv;
        g_outn[(size_t)r * D_DIM + d] = on;
        g_qh[(size_t)r * D_DIM + d] = __float2half_rn(on - erow[d]);
    }
    if (threadIdx.x == 0) g_best[r] = 0ull;
}

// ---------------------------------------------------------------------------
// Kernel 3: fp16 mma.sync GEMM, 3-stage cp.async (1 barrier/chunk), 2 CTAs/SM,
// XOR-swizzled SMEM, fused vinv-scale + argmax. CTA 128x160, warp tile 32x80.
// ---------------------------------------------------------------------------
__global__ void __launch_bounds__(256, 2) gemm_mma_kernel() {
    extern __shared__ char smem[];
    const uint32_t sb = smem_u32(smem);
    const int tid  = threadIdx.x;
    const int wid  = tid >> 5;
    const int lane = tid & 31;
    const int mblk = blockIdx.x * MT;
    const int nblk = blockIdx.y * NT;
    const int warp_m = (wid & 3) * 32;      // 4 warps along M
    const int warp_n = (wid >> 2) * 80;     // 2 warps along N

    const __half* Aqh = g_qh + (size_t)mblk * D_DIM;
    const __half* Beh = g_eh + (size_t)nblk * D_DIM;

    auto load_chunk = [&](int slot, int ch) {
        int kc = ch * KC;
        uint32_t st = sb + slot * STAGE;
        // A: 128 rows * 8 chunks(16B) = 1024 -> 4 per thread
#pragma unroll
        for (int i = 0; i < 4; i++) {
            int s = tid + i * 256;
            int row = s >> 3, c = s & 7;
            cp16(st + A_OFF + swz(row, c), Aqh + (size_t)row * D_DIM + kc + c * 8);
        }
        // B: 160 rows * 8 chunks = 1280 -> 5 per thread
#pragma unroll
        for (int i = 0; i < 5; i++) {
            int s = tid + i * 256;
            int row = s >> 3, c = s & 7;
            cp16(st + B_OFF + swz(row, c), Beh + (size_t)row * D_DIM + kc + c * 8);
        }
    };

    float acc[2][10][4];
#pragma unroll
    for (int i = 0; i < 2; i++)
#pragma unroll
        for (int j = 0; j < 10; j++)
#pragma unroll
            for (int k = 0; k < 4; k++) acc[i][j][k] = 0.f;

    load_chunk(0, 0); CP_COMMIT();
    load_chunk(1, 1); CP_COMMIT();

    for (int it = 0; it < NCHUNK; it++) {
        if (it + 1 < NCHUNK) { CP_WAIT1(); } else { CP_WAIT0(); }
        __syncthreads();   // chunk `it` visible to all warps; all warps past compute(it-1)

        if (it + 2 < NCHUNK) {
            load_chunk((it + 2) % NSTAGE, it + 2);   // slot was consumed at it-1
            CP_COMMIT();
        }

        uint32_t st  = sb + (it % NSTAGE) * STAGE;
        uint32_t sa  = st + A_OFF;
        uint32_t sbm = st + B_OFF;
#pragma unroll
        for (int ks = 0; ks < 4; ks++) {
            int k = ks * 16;
            uint32_t a[2][4];
#pragma unroll
            for (int mi = 0; mi < 2; mi++) {
                int row = warp_m + mi * 16 + (lane & 15);
                int kch = (k >> 3) + (lane >> 4);
                ldsm_x4(sa + swz(row, kch), a[mi][0], a[mi][1], a[mi][2], a[mi][3]);
            }
#pragma unroll
            for (int bj = 0; bj < 5; bj++) {
                uint32_t b0[2], b1[2];
                int n   = warp_n + bj * 16 + (lane & 7) + ((lane >> 4) & 1) * 8;
                int kch = (k >> 3) + ((lane >> 3) & 1);
                ldsm_x4(sbm + swz(n, kch), b0[0], b0[1], b1[0], b1[1]);
#pragma unroll
                for (int mi = 0; mi < 2; mi++) {
                    mma16816(acc[mi][bj * 2],     a[mi], b0);
                    mma16816(acc[mi][bj * 2 + 1], a[mi], b1);
                }
            }
        }
        // no trailing sync: next iteration's barrier orders slot reuse
    }
    __syncthreads();   // all compute done before smem reuse below

    // stage vinv for this N tile (160 floats)
    if (tid < NT) ((float*)smem)[tid] = g_vinv[nblk + tid];
    __syncthreads();
    const float* vin = (const float*)smem;

    // argmax epilogue: rows r0 = warp_m + mi*16 + lane/4 (+8), cols warp_n + nj*8 + 2*(lane&3)
#pragma unroll
    for (int mi = 0; mi < 2; mi++) {
        float bv0 = -1e30f, bv1 = -1e30f;
        int   bj0 = 0,      bj1 = 0;
#pragma unroll
        for (int nj = 0; nj < 10; nj++) {
            int c0 = warp_n + nj * 8 + 2 * (lane & 3);
            float v00 = acc[mi][nj][0] * vin[c0];
            float v01 = acc[mi][nj][1] * vin[c0 + 1];
            float v10 = acc[mi][nj][2] * vin[c0];
            float v11 = acc[mi][nj][3] * vin[c0 + 1];
            if (v00 > bv0) { bv0 = v00; bj0 = c0; }
            if (v01 > bv0) { bv0 = v01; bj0 = c0 + 1; }
            if (v10 > bv1) { bv1 = v10; bj1 = c0; }
            if (v11 > bv1) { bv1 = v11; bj1 = c0 + 1; }
        }
#pragma unroll
        for (int off = 1; off < 4; off <<= 1) {
            float o0 = __shfl_xor_sync(0xffffffffu, bv0, off);
            int   j0 = __shfl_xor_sync(0xffffffffu, bj0, off);
            float o1 = __shfl_xor_sync(0xffffffffu, bv1, off);
            int   j1 = __shfl_xor_sync(0xffffffffu, bj1, off);
            if (o0 > bv0 || (o0 == bv0 && j0 < bj0)) { bv0 = o0; bj0 = j0; }
            if (o1 > bv1 || (o1 == bv1 && j1 < bj1)) { bv1 = o1; bj1 = j1; }
        }
        if ((lane & 3) == 0) {
            int r0 = mblk + warp_m + mi * 16 + (lane >> 2);
            atomicMax(&g_best[r0],     enc_key(bv0, (unsigned)(nblk + bj0)));
            atomicMax(&g_best[r0 + 8], enc_key(bv1, (unsigned)(nblk + bj1)));
        }
    }
}

// ---------------------------------------------------------------------------
// Kernel 4: per-row hinge in exact fp32. One warp per row.
// ---------------------------------------------------------------------------
__global__ void finalize_kernel(const float* __restrict__ emb,
                                const int* __restrict__ target,
                                const int* __restrict__ pad) {
    int r    = blockIdx.x * 8 + (threadIdx.x >> 5);
    int lane = threadIdx.x & 31;
    int t = clamp_idx(target[r]);
    unsigned long long key = g_best[r];
    int jm = clamp_idx((int)(0x7fffffffu - (unsigned)(key & 0xffffffffu)));

    const float* on = g_outn + (size_t)r * D_DIM;
    const float* e1 = emb + (size_t)t  * D_DIM;
    const float* e2 = emb + (size_t)jm * D_DIM;
    float d1 = 0.f, d2 = 0.f;
#pragma unroll
    for (int d = lane; d < D_DIM; d += 32) {
        float o = on[d];
        d1 = fmaf(o, e1[d], d1);
        d2 = fmaf(o, e2[d], d2);
    }
#pragma unroll
    for (int off = 16; off; off >>= 1) {
        d1 += __shfl_xor_sync(0xffffffffu, d1, off);
        d2 += __shfl_xor_sync(0xffffffffu, d2, off);
    }
    if (lane == 0) {
        d1 *= g_vinv[t];
        d2 *= g_vinv[jm];
        float df = fmaxf(GAMMA_F + d2 - d1, 0.f);
        g_diff[r] = (target[r] != *pad) ? df : 0.f;
    }
}

// ---------------------------------------------------------------------------
// Kernel 5: deterministic scalar reduction
// ---------------------------------------------------------------------------
__global__ void reduce_kernel(const int* __restrict__ target,
                              const int* __restrict__ pad,
                              float* __restrict__ out) {
    __shared__ float ssum[1024];
    __shared__ float scnt[1024];
    int t = threadIdx.x;
    int p = *pad;
    float s = 0.f, c = 0.f;
    for (int r = t; r < BS_ROWS; r += 1024) {
        s += g_diff[r];
        c += (target[r] != p) ? 1.f : 0.f;
    }
    ssum[t] = s; scnt[t] = c; __syncthreads();
    for (int off = 512; off; off >>= 1) {
        if (t < off) { ssum[t] += ssum[t + off]; scnt[t] += scnt[t + off]; }
        __syncthreads();
    }
    if (t == 0) out[0] = ssum[0] / scnt[0];
}

// ---------------------------------------------------------------------------
extern "C" void kernel_launch(void* const* d_in, const int* in_sizes, int n_in,
                              void* d_out, int out_size) {
    const float* preds  = (const float*)d_in[0];
    const float* emb    = (const float*)d_in[1];
    const int*   target = (const int*)d_in[2];
    const int*   pad    = (const int*)d_in[3];

    cudaFuncSetAttribute(gemm_mma_kernel, cudaFuncAttributeMaxDynamicSharedMemorySize, SMEMSZ);

    vsplit_kernel<<<V_DIM, 128>>>(emb);
    prep_kernel<<<BS_ROWS, 128>>>(preds, emb, target);
    dim3 grid(BS_ROWS / MT, V_DIM / NT);   // (16, 200)
    gemm_mma_kernel<<<grid, 256, SMEMSZ>>>();
    finalize_kernel<<<BS_ROWS / 8, 256>>>(emb, target, pad);
    reduce_kernel<<<1, 1024>>>(target, pad, (float*)d_out);
}

// round 9
// speedup vs baseline: 7.3382x; 1.0232x over previous
#include <cuda_runtime.h>
#include <cuda_fp16.h>
#include <math.h>
#include <stdint.h>

// Problem constants
#define D_DIM   512
#define V_DIM   32000
#define BS_ROWS 2048
#define GAMMA_F 0.5f
#define EPS_F   1e-12f

// GEMM tiling: CTA 128x160, 8 warps (warp tile 32x80), 2 CTAs/SM
#define MT 128
#define NT 160
#define KC 64               // fp16 K per chunk (128 B rows)
#define NCHUNK 8            // 512 / 64
#define NSTAGE 3

// SMEM: 128B rows with XOR swizzle (chunk ^= row&7) -> conflict-free ldmatrix
#define ROWB   128
#define A_OFF  0
#define B_OFF  (MT * ROWB)               // 16384
#define STAGE  ((MT + NT) * ROWB)        // 36864
#define SMEMSZ (NSTAGE * STAGE)          // 110592

// ---------------------------------------------------------------------------
// Static scratch
// ---------------------------------------------------------------------------
__device__ __half g_qh[BS_ROWS * D_DIM];
__device__ __half g_eh[(size_t)V_DIM * D_DIM];
__device__ float              g_vinv[V_DIM];
__device__ float              g_outn[BS_ROWS * D_DIM];
__device__ unsigned long long g_best[BS_ROWS];
__device__ float              g_diff[BS_ROWS];

// ---------------------------------------------------------------------------
// helpers
// ---------------------------------------------------------------------------
__device__ __forceinline__ uint32_t smem_u32(const void* p) {
    uint32_t a;
    asm("{ .reg .u64 t; cvta.to.shared.u64 t, %1; cvt.u32.u64 %0, t; }" : "=r"(a) : "l"(p));
    return a;
}
__device__ __forceinline__ void cp16(uint32_t dst, const void* src) {
    asm volatile("cp.async.cg.shared.global [%0], [%1], 16;" :: "r"(dst), "l"(src));
}
#define CP_COMMIT() asm volatile("cp.async.commit_group;" ::: "memory")
#define CP_WAIT1()  asm volatile("cp.async.wait_group 1;" ::: "memory")
#define CP_WAIT0()  asm volatile("cp.async.wait_group 0;" ::: "memory")

__device__ __forceinline__ void ldsm_x4(uint32_t addr, uint32_t& r0, uint32_t& r1,
                                        uint32_t& r2, uint32_t& r3) {
    asm volatile("ldmatrix.sync.aligned.m8n8.x4.shared.b16 {%0,%1,%2,%3}, [%4];"
                 : "=r"(r0), "=r"(r1), "=r"(r2), "=r"(r3) : "r"(addr));
}
__device__ __forceinline__ void mma16816(float* c, const uint32_t* a, const uint32_t* b) {
    asm volatile(
        "mma.sync.aligned.m16n8k16.row.col.f32.f16.f16.f32 "
        "{%0,%1,%2,%3}, {%4,%5,%6,%7}, {%8,%9}, {%0,%1,%2,%3};"
        : "+f"(c[0]), "+f"(c[1]), "+f"(c[2]), "+f"(c[3])
        : "r"(a[0]), "r"(a[1]), "r"(a[2]), "r"(a[3]), "r"(b[0]), "r"(b[1]));
}

// XOR swizzle: 16B chunk index within a 128B row, xored with row&7
__device__ __forceinline__ uint32_t swz(uint32_t row, uint32_t chunk) {
    return row * ROWB + ((chunk ^ (row & 7u)) << 4);
}

// Monotone (score, idx) packing; bigger score wins, tie -> smaller index
__device__ __forceinline__ unsigned long long enc_key(float v, unsigned idx) {
    unsigned u = __float_as_uint(v);
    u = (u & 0x80000000u) ? ~u : (u | 0x80000000u);
    return ((unsigned long long)u << 32) | (unsigned long long)(0x7fffffffu - idx);
}
__device__ __forceinline__ int clamp_idx(int t) {
    t = t < 0 ? 0 : t;
    return t >= V_DIM ? V_DIM - 1 : t;
}

// ---------------------------------------------------------------------------
// Kernel 1: vocab pass — vinv + fp16 copy. One WARP per row, shuffle-only.
// ---------------------------------------------------------------------------
__global__ void __launch_bounds__(256) vsplit_kernel(const float* __restrict__ emb) {
    int gw   = (blockIdx.x * 256 + threadIdx.x) >> 5;   // global warp = vocab row
    int lane = threadIdx.x & 31;
    const float4* row = (const float4*)(emb + (size_t)gw * D_DIM);

    float4 v[4];
    float ss = 0.f;
#pragma unroll
    for (int k = 0; k < 4; k++) {
        v[k] = row[lane + 32 * k];
        ss = fmaf(v[k].x, v[k].x, ss);
        ss = fmaf(v[k].y, v[k].y, ss);
        ss = fmaf(v[k].z, v[k].z, ss);
        ss = fmaf(v[k].w, v[k].w, ss);
    }
#pragma unroll
    for (int off = 16; off; off >>= 1) ss += __shfl_xor_sync(0xffffffffu, ss, off);
    if (lane == 0) g_vinv[gw] = 1.f / fmaxf(sqrtf(ss), EPS_F);

#pragma unroll
    for (int k = 0; k < 4; k++) {
        size_t base = (size_t)gw * D_DIM + (lane + 32 * k) * 4;
        *(__half2*)(g_eh + base)     = __halves2half2(__float2half_rn(v[k].x), __float2half_rn(v[k].y));
        *(__half2*)(g_eh + base + 2) = __halves2half2(__float2half_rn(v[k].z), __float2half_rn(v[k].w));
    }
}

// ---------------------------------------------------------------------------
// Kernel 2: prep — coalesced transpose of preds columns.
// Block = one (batch, 16-seq tile). Grid 128, 256 threads.
// Pass 1: norms with sector-aligned reads. Pass 2: smem-staged transpose,
// contiguous writes of out_norm (fp32) and q = out_norm - emb[target] (fp16).
// Also resets g_best.
// ---------------------------------------------------------------------------
#define ST 16
__global__ void __launch_bounds__(256) prep_kernel(const float* __restrict__ preds,
                                                   const float* __restrict__ emb,
                                                   const int* __restrict__ target) {
    __shared__ float tile[64][17];
    __shared__ float part[16][17];
    __shared__ float inv_s[ST];
    __shared__ int   tgt_s[ST];

    int blk = blockIdx.x;               // 0..127
    int b   = blk >> 5;                 // 4 batches x 32 s-tiles
    int s0  = (blk & 31) * ST;
    int t   = threadIdx.x;
    const float* P = preds + (size_t)b * D_DIM * 512 + s0;

    // pass 1: per-seq sum of squares. thread: ss = t&15, dr = t>>4
    int ss = t & 15, dr = t >> 4;
    float acc = 0.f;
    for (int d0 = 0; d0 < D_DIM; d0 += 16)
        { float x = P[(size_t)(d0 + dr) * 512 + ss]; acc = fmaf(x, x, acc); }
    part[dr][ss] = acc;
    __syncthreads();
    if (t < ST) {
        float n = 0.f;
#pragma unroll
        for (int i = 0; i < 16; i++) n += part[i][t];
        inv_s[t] = 1.f / fmaxf(sqrtf(n), EPS_F);
        int r = b * 512 + s0 + t;
        tgt_s[t] = clamp_idx(target[r]);
        g_best[r] = 0ull;
    }
    __syncthreads();

    // pass 2: 8 chunks of 64 d; stage [64 d x 16 s] then write transposed
    for (int d0 = 0; d0 < D_DIM; d0 += 64) {
#pragma unroll
        for (int i = 0; i < 4; i++) {
            int dd = (t >> 4) + i * 16;
            tile[dd][ss] = P[(size_t)(d0 + dd) * 512 + ss];
        }
        __syncthreads();
        int ss2  = t >> 4;                 // 0..15 seq row
        int dcol = (t & 15) * 4;           // 4 consecutive d
        float inv = inv_s[ss2];
        int r = b * 512 + s0 + ss2;
        const float* erow = emb + (size_t)tgt_s[ss2] * D_DIM + d0 + dcol;
        float4 o;
        __half hq[4];
        float* ov = &o.x;
#pragma unroll
        for (int j = 0; j < 4; j++) {
            float on = tile[dcol + j][ss2] * inv;
            ov[j] = on;
            hq[j] = __float2half_rn(on - erow[j]);
        }
        *(float4*)(g_outn + (size_t)r * D_DIM + d0 + dcol) = o;
        *(__half2*)(g_qh + (size_t)r * D_DIM + d0 + dcol)     = __halves2half2(hq[0], hq[1]);
        *(__half2*)(g_qh + (size_t)r * D_DIM + d0 + dcol + 2) = __halves2half2(hq[2], hq[3]);
        __syncthreads();
    }
}

// ---------------------------------------------------------------------------
// Kernel 3: fp16 mma.sync GEMM, 3-stage cp.async (1 barrier/chunk), 2 CTAs/SM,
// XOR-swizzled SMEM, fused vinv-scale + argmax. CTA 128x160, warp tile 32x80.
// ---------------------------------------------------------------------------
__global__ void __launch_bounds__(256, 2) gemm_mma_kernel() {
    extern __shared__ char smem[];
    const uint32_t sb = smem_u32(smem);
    const int tid  = threadIdx.x;
    const int wid  = tid >> 5;
    const int lane = tid & 31;
    const int mblk = blockIdx.x * MT;
    const int nblk = blockIdx.y * NT;
    const int warp_m = (wid & 3) * 32;      // 4 warps along M
    const int warp_n = (wid >> 2) * 80;     // 2 warps along N

    const __half* Aqh = g_qh + (size_t)mblk * D_DIM;
    const __half* Beh = g_eh + (size_t)nblk * D_DIM;

    auto load_chunk = [&](int slot, int ch) {
        int kc = ch * KC;
        uint32_t st = sb + slot * STAGE;
#pragma unroll
        for (int i = 0; i < 4; i++) {
            int s = tid + i * 256;
            int row = s >> 3, c = s & 7;
            cp16(st + A_OFF + swz(row, c), Aqh + (size_t)row * D_DIM + kc + c * 8);
        }
#pragma unroll
        for (int i = 0; i < 5; i++) {
            int s = tid + i * 256;
            int row = s >> 3, c = s & 7;
            cp16(st + B_OFF + swz(row, c), Beh + (size_t)row * D_DIM + kc + c * 8);
        }
    };

    float acc[2][10][4];
#pragma unroll
    for (int i = 0; i < 2; i++)
#pragma unroll
        for (int j = 0; j < 10; j++)
#pragma unroll
            for (int k = 0; k < 4; k++) acc[i][j][k] = 0.f;

    load_chunk(0, 0); CP_COMMIT();
    load_chunk(1, 1); CP_COMMIT();

    for (int it = 0; it < NCHUNK; it++) {
        if (it + 1 < NCHUNK) { CP_WAIT1(); } else { CP_WAIT0(); }
        __syncthreads();

        if (it + 2 < NCHUNK) {
            load_chunk((it + 2) % NSTAGE, it + 2);
            CP_COMMIT();
        }

        uint32_t st  = sb + (it % NSTAGE) * STAGE;
        uint32_t sa  = st + A_OFF;
        uint32_t sbm = st + B_OFF;
#pragma unroll
        for (int ks = 0; ks < 4; ks++) {
            int k = ks * 16;
            uint32_t a[2][4];
#pragma unroll
            for (int mi = 0; mi < 2; mi++) {
                int row = warp_m + mi * 16 + (lane & 15);
                int kch = (k >> 3) + (lane >> 4);
                ldsm_x4(sa + swz(row, kch), a[mi][0], a[mi][1], a[mi][2], a[mi][3]);
            }
#pragma unroll
            for (int bj = 0; bj < 5; bj++) {
                uint32_t b0[2], b1[2];
                int n   = warp_n + bj * 16 + (lane & 7) + ((lane >> 4) & 1) * 8;
                int kch = (k >> 3) + ((lane >> 3) & 1);
                ldsm_x4(sbm + swz(n, kch), b0[0], b0[1], b1[0], b1[1]);
#pragma unroll
                for (int mi = 0; mi < 2; mi++) {
                    mma16816(acc[mi][bj * 2],     a[mi], b0);
                    mma16816(acc[mi][bj * 2 + 1], a[mi], b1);
                }
            }
        }
    }
    __syncthreads();

    if (tid < NT) ((float*)smem)[tid] = g_vinv[nblk + tid];
    __syncthreads();
    const float* vin = (const float*)smem;

#pragma unroll
    for (int mi = 0; mi < 2; mi++) {
        float bv0 = -1e30f, bv1 = -1e30f;
        int   bj0 = 0,      bj1 = 0;
#pragma unroll
        for (int nj = 0; nj < 10; nj++) {
            int c0 = warp_n + nj * 8 + 2 * (lane & 3);
            float v00 = acc[mi][nj][0] * vin[c0];
            float v01 = acc[mi][nj][1] * vin[c0 + 1];
            float v10 = acc[mi][nj][2] * vin[c0];
            float v11 = acc[mi][nj][3] * vin[c0 + 1];
            if (v00 > bv0) { bv0 = v00; bj0 = c0; }
            if (v01 > bv0) { bv0 = v01; bj0 = c0 + 1; }
            if (v10 > bv1) { bv1 = v10; bj1 = c0; }
            if (v11 > bv1) { bv1 = v11; bj1 = c0 + 1; }
        }
#pragma unroll
        for (int off = 1; off < 4; off <<= 1) {
            float o0 = __shfl_xor_sync(0xffffffffu, bv0, off);
            int   j0 = __shfl_xor_sync(0xffffffffu, bj0, off);
            float o1 = __shfl_xor_sync(0xffffffffu, bv1, off);
            int   j1 = __shfl_xor_sync(0xffffffffu, bj1, off);
            if (o0 > bv0 || (o0 == bv0 && j0 < bj0)) { bv0 = o0; bj0 = j0; }
            if (o1 > bv1 || (o1 == bv1 && j1 < bj1)) { bv1 = o1; bj1 = j1; }
        }
        if ((lane & 3) == 0) {
            int r0 = mblk + warp_m + mi * 16 + (lane >> 2);
            atomicMax(&g_best[r0],     enc_key(bv0, (unsigned)(nblk + bj0)));
            atomicMax(&g_best[r0 + 8], enc_key(bv1, (unsigned)(nblk + bj1)));
        }
    }
}

// ---------------------------------------------------------------------------
// Kernel 4: per-row hinge in exact fp32. One warp per row.
// ---------------------------------------------------------------------------
__global__ void finalize_kernel(const float* __restrict__ emb,
                                const int* __restrict__ target,
                                const int* __restrict__ pad) {
    int r    = blockIdx.x * 8 + (threadIdx.x >> 5);
    int lane = threadIdx.x & 31;
    int t = clamp_idx(target[r]);
    unsigned long long key = g_best[r];
    int jm = clamp_idx((int)(0x7fffffffu - (unsigned)(key & 0xffffffffu)));

    const float* on = g_outn + (size_t)r * D_DIM;
    const float* e1 = emb + (size_t)t  * D_DIM;
    const float* e2 = emb + (size_t)jm * D_DIM;
    float d1 = 0.f, d2 = 0.f;
#pragma unroll
    for (int d = lane; d < D_DIM; d += 32) {
        float o = on[d];
        d1 = fmaf(o, e1[d], d1);
        d2 = fmaf(o, e2[d], d2);
    }
#pragma unroll
    for (int off = 16; off; off >>= 1) {
        d1 += __shfl_xor_sync(0xffffffffu, d1, off);
        d2 += __shfl_xor_sync(0xffffffffu, d2, off);
    }
    if (lane == 0) {
        d1 *= g_vinv[t];
        d2 *= g_vinv[jm];
        float df = fmaxf(GAMMA_F + d2 - d1, 0.f);
        g_diff[r] = (target[r] != *pad) ? df : 0.f;
    }
}

// ---------------------------------------------------------------------------
// Kernel 5: deterministic scalar reduction
// ---------------------------------------------------------------------------
__global__ void reduce_kernel(const int* __restrict__ target,
                              const int* __restrict__ pad,
                              float* __restrict__ out) {
    __shared__ float ssum[1024];
    __shared__ float scnt[1024];
    int t = threadIdx.x;
    int p = *pad;
    float s = 0.f, c = 0.f;
    for (int r = t; r < BS_ROWS; r += 1024) {
        s += g_diff[r];
        c += (target[r] != p) ? 1.f : 0.f;
    }
    ssum[t] = s; scnt[t] = c; __syncthreads();
    for (int off = 512; off; off >>= 1) {
        if (t < off) { ssum[t] += ssum[t + off]; scnt[t] += scnt[t + off]; }
        __syncthreads();
    }
    if (t == 0) out[0] = ssum[0] / scnt[0];
}

// ---------------------------------------------------------------------------
extern "C" void kernel_launch(void* const* d_in, const int* in_sizes, int n_in,
                              void* d_out, int out_size) {
    const float* preds  = (const float*)d_in[0];
    const float* emb    = (const float*)d_in[1];
    const int*   target = (const int*)d_in[2];
    const int*   pad    = (const int*)d_in[3];

    cudaFuncSetAttribute(gemm_mma_kernel, cudaFuncAttributeMaxDynamicSharedMemorySize, SMEMSZ);

    vsplit_kernel<<<V_DIM / 8, 256>>>(emb);              // warp per row
    prep_kernel<<<128, 256>>>(preds, emb, target);       // coalesced transpose
    dim3 grid(BS_ROWS / MT, V_DIM / NT);                 // (16, 200)
    gemm_mma_kernel<<<grid, 256, SMEMSZ>>>();
    finalize_kernel<<<BS_ROWS / 8, 256>>>(emb, target, pad);
    reduce_kernel<<<1, 1024>>>(target, pad, (float*)d_out);
}

// round 10
// speedup vs baseline: 7.3998x; 1.0084x over previous
#include <cuda_runtime.h>
#include <cuda_fp16.h>
#include <math.h>
#include <stdint.h>

// Problem constants
#define D_DIM   512
#define V_DIM   32000
#define BS_ROWS 2048
#define GAMMA_F 0.5f
#define EPS_F   1e-12f

// GEMM tiling: CTA 128x160, 8 warps (warp tile 32x80), 2 CTAs/SM
#define MT 128
#define NT 160
#define KC 64               // fp16 K per chunk (128 B rows)
#define NCHUNK 8            // 512 / 64
#define NSTAGE 3

// SMEM: 128B rows with XOR swizzle (chunk ^= row&7) -> conflict-free ldmatrix
#define ROWB   128
#define A_OFF  0
#define B_OFF  (MT * ROWB)               // 16384
#define STAGE  ((MT + NT) * ROWB)        // 36864
#define V_OFF  (NSTAGE * STAGE)          // 110592 : vinv staging (160 floats)
#define SMEMSZ (V_OFF + NT * 4)          // 111232

// ---------------------------------------------------------------------------
// Static scratch
// ---------------------------------------------------------------------------
__device__ __half g_qh[BS_ROWS * D_DIM];
__device__ __half g_eh[(size_t)V_DIM * D_DIM];
__device__ float              g_vinv[V_DIM];
__device__ float              g_outn[BS_ROWS * D_DIM];
__device__ unsigned long long g_best[BS_ROWS];
__device__ float              g_diff[BS_ROWS];
__device__ int                g_cnt;     // zero-initialized; self-resetting

// ---------------------------------------------------------------------------
// helpers
// ---------------------------------------------------------------------------
__device__ __forceinline__ uint32_t smem_u32(const void* p) {
    uint32_t a;
    asm("{ .reg .u64 t; cvta.to.shared.u64 t, %1; cvt.u32.u64 %0, t; }" : "=r"(a) : "l"(p));
    return a;
}
__device__ __forceinline__ void cp16(uint32_t dst, const void* src) {
    asm volatile("cp.async.cg.shared.global [%0], [%1], 16;" :: "r"(dst), "l"(src));
}
#define CP_COMMIT() asm volatile("cp.async.commit_group;" ::: "memory")
#define CP_WAIT1()  asm volatile("cp.async.wait_group 1;" ::: "memory")
#define CP_WAIT0()  asm volatile("cp.async.wait_group 0;" ::: "memory")

__device__ __forceinline__ void ldsm_x4(uint32_t addr, uint32_t& r0, uint32_t& r1,
                                        uint32_t& r2, uint32_t& r3) {
    asm volatile("ldmatrix.sync.aligned.m8n8.x4.shared.b16 {%0,%1,%2,%3}, [%4];"
                 : "=r"(r0), "=r"(r1), "=r"(r2), "=r"(r3) : "r"(addr));
}
__device__ __forceinline__ void mma16816(float* c, const uint32_t* a, const uint32_t* b) {
    asm volatile(
        "mma.sync.aligned.m16n8k16.row.col.f32.f16.f16.f32 "
        "{%0,%1,%2,%3}, {%4,%5,%6,%7}, {%8,%9}, {%0,%1,%2,%3};"
        : "+f"(c[0]), "+f"(c[1]), "+f"(c[2]), "+f"(c[3])
        : "r"(a[0]), "r"(a[1]), "r"(a[2]), "r"(a[3]), "r"(b[0]), "r"(b[1]));
}

// XOR swizzle: 16B chunk index within a 128B row, xored with row&7
__device__ __forceinline__ uint32_t swz(uint32_t row, uint32_t chunk) {
    return row * ROWB + ((chunk ^ (row & 7u)) << 4);
}

// Monotone (score, idx) packing; bigger score wins, tie -> smaller index
__device__ __forceinline__ unsigned long long enc_key(float v, unsigned idx) {
    unsigned u = __float_as_uint(v);
    u = (u & 0x80000000u) ? ~u : (u | 0x80000000u);
    return ((unsigned long long)u << 32) | (unsigned long long)(0x7fffffffu - idx);
}
__device__ __forceinline__ int clamp_idx(int t) {
    t = t < 0 ? 0 : t;
    return t >= V_DIM ? V_DIM - 1 : t;
}

// ---------------------------------------------------------------------------
// Kernel 1 (merged): blocks [0,4000) = vocab pass (warp/row, shuffle-only);
// blocks [4000,4128) = preds transpose + q build. Independent -> concurrent.
// ---------------------------------------------------------------------------
#define ST 16
#define VBLKS (V_DIM / 8)     // 4000
__global__ void __launch_bounds__(256) pre_kernel(const float* __restrict__ emb,
                                                  const float* __restrict__ preds,
                                                  const int* __restrict__ target) {
    __shared__ float tile[64][17];
    __shared__ float part[16][17];
    __shared__ float inv_s[ST];
    __shared__ int   tgt_s[ST];

    if (blockIdx.x < VBLKS) {
        // ------- vocab role: 8 warps, one vocab row each -------
        int gw   = (blockIdx.x * 256 + threadIdx.x) >> 5;
        int lane = threadIdx.x & 31;
        const float4* row = (const float4*)(emb + (size_t)gw * D_DIM);
        float4 v[4];
        float ss = 0.f;
#pragma unroll
        for (int k = 0; k < 4; k++) {
            v[k] = row[lane + 32 * k];
            ss = fmaf(v[k].x, v[k].x, ss);
            ss = fmaf(v[k].y, v[k].y, ss);
            ss = fmaf(v[k].z, v[k].z, ss);
            ss = fmaf(v[k].w, v[k].w, ss);
        }
#pragma unroll
        for (int off = 16; off; off >>= 1) ss += __shfl_xor_sync(0xffffffffu, ss, off);
        if (lane == 0) g_vinv[gw] = 1.f / fmaxf(sqrtf(ss), EPS_F);
#pragma unroll
        for (int k = 0; k < 4; k++) {
            size_t base = (size_t)gw * D_DIM + (lane + 32 * k) * 4;
            *(__half2*)(g_eh + base)     = __halves2half2(__float2half_rn(v[k].x), __float2half_rn(v[k].y));
            *(__half2*)(g_eh + base + 2) = __halves2half2(__float2half_rn(v[k].z), __float2half_rn(v[k].w));
        }
        return;
    }

    // ------- prep role: coalesced transpose of preds columns -------
    int blk = blockIdx.x - VBLKS;       // 0..127
    int b   = blk >> 5;                 // 4 batches x 32 s-tiles
    int s0  = (blk & 31) * ST;
    int t   = threadIdx.x;
    const float* P = preds + (size_t)b * D_DIM * 512 + s0;

    int ss = t & 15, dr = t >> 4;
    float acc = 0.f;
    for (int d0 = 0; d0 < D_DIM; d0 += 16)
        { float x = P[(size_t)(d0 + dr) * 512 + ss]; acc = fmaf(x, x, acc); }
    part[dr][ss] = acc;
    __syncthreads();
    if (t < ST) {
        float n = 0.f;
#pragma unroll
        for (int i = 0; i < 16; i++) n += part[i][t];
        inv_s[t] = 1.f / fmaxf(sqrtf(n), EPS_F);
        int r = b * 512 + s0 + t;
        tgt_s[t] = clamp_idx(target[r]);
        g_best[r] = 0ull;
    }
    __syncthreads();

    for (int d0 = 0; d0 < D_DIM; d0 += 64) {
#pragma unroll
        for (int i = 0; i < 4; i++) {
            int dd = (t >> 4) + i * 16;
            tile[dd][ss] = P[(size_t)(d0 + dd) * 512 + ss];
        }
        __syncthreads();
        int ss2  = t >> 4;
        int dcol = (t & 15) * 4;
        float inv = inv_s[ss2];
        int r = b * 512 + s0 + ss2;
        const float* erow = emb + (size_t)tgt_s[ss2] * D_DIM + d0 + dcol;
        float4 o;
        __half hq[4];
        float* ov = &o.x;
#pragma unroll
        for (int j = 0; j < 4; j++) {
            float on = tile[dcol + j][ss2] * inv;
            ov[j] = on;
            hq[j] = __float2half_rn(on - erow[j]);
        }
        *(float4*)(g_outn + (size_t)r * D_DIM + d0 + dcol) = o;
        *(__half2*)(g_qh + (size_t)r * D_DIM + d0 + dcol)     = __halves2half2(hq[0], hq[1]);
        *(__half2*)(g_qh + (size_t)r * D_DIM + d0 + dcol + 2) = __halves2half2(hq[2], hq[3]);
        __syncthreads();
    }
}

// ---------------------------------------------------------------------------
// Kernel 2: fp16 mma.sync GEMM, 3-stage cp.async (1 barrier/chunk), 2 CTAs/SM,
// XOR-swizzled SMEM, vinv prefetched pre-loop, fused argmax epilogue (no
// epilogue barriers). CTA 128x160, warp tile 32x80.
// ---------------------------------------------------------------------------
__global__ void __launch_bounds__(256, 2) gemm_mma_kernel() {
    extern __shared__ char smem[];
    const uint32_t sb = smem_u32(smem);
    const int tid  = threadIdx.x;
    const int wid  = tid >> 5;
    const int lane = tid & 31;
    const int mblk = blockIdx.x * MT;
    const int nblk = blockIdx.y * NT;
    const int warp_m = (wid & 3) * 32;      // 4 warps along M
    const int warp_n = (wid >> 2) * 80;     // 2 warps along N

    const __half* Aqh = g_qh + (size_t)mblk * D_DIM;
    const __half* Beh = g_eh + (size_t)nblk * D_DIM;

    // prefetch vinv for this N tile into its own smem region; the in-loop
    // barriers make it visible to all threads before the epilogue reads it.
    if (tid < NT) ((float*)(smem + V_OFF))[tid] = g_vinv[nblk + tid];

    auto load_chunk = [&](int slot, int ch) {
        int kc = ch * KC;
        uint32_t st = sb + slot * STAGE;
#pragma unroll
        for (int i = 0; i < 4; i++) {
            int s = tid + i * 256;
            int row = s >> 3, c = s & 7;
            cp16(st + A_OFF + swz(row, c), Aqh + (size_t)row * D_DIM + kc + c * 8);
        }
#pragma unroll
        for (int i = 0; i < 5; i++) {
            int s = tid + i * 256;
            int row = s >> 3, c = s & 7;
            cp16(st + B_OFF + swz(row, c), Beh + (size_t)row * D_DIM + kc + c * 8);
        }
    };

    float acc[2][10][4];
#pragma unroll
    for (int i = 0; i < 2; i++)
#pragma unroll
        for (int j = 0; j < 10; j++)
#pragma unroll
            for (int k = 0; k < 4; k++) acc[i][j][k] = 0.f;

    load_chunk(0, 0); CP_COMMIT();
    load_chunk(1, 1); CP_COMMIT();

    for (int it = 0; it < NCHUNK; it++) {
        if (it + 1 < NCHUNK) { CP_WAIT1(); } else { CP_WAIT0(); }
        __syncthreads();

        if (it + 2 < NCHUNK) {
            load_chunk((it + 2) % NSTAGE, it + 2);
            CP_COMMIT();
        }

        uint32_t st  = sb + (it % NSTAGE) * STAGE;
        uint32_t sa  = st + A_OFF;
        uint32_t sbm = st + B_OFF;
#pragma unroll
        for (int ks = 0; ks < 4; ks++) {
            int k = ks * 16;
            uint32_t a[2][4];
#pragma unroll
            for (int mi = 0; mi < 2; mi++) {
                int row = warp_m + mi * 16 + (lane & 15);
                int kch = (k >> 3) + (lane >> 4);
                ldsm_x4(sa + swz(row, kch), a[mi][0], a[mi][1], a[mi][2], a[mi][3]);
            }
#pragma unroll
            for (int bj = 0; bj < 5; bj++) {
                uint32_t b0[2], b1[2];
                int n   = warp_n + bj * 16 + (lane & 7) + ((lane >> 4) & 1) * 8;
                int kch = (k >> 3) + ((lane >> 3) & 1);
                ldsm_x4(sbm + swz(n, kch), b0[0], b0[1], b1[0], b1[1]);
#pragma unroll
                for (int mi = 0; mi < 2; mi++) {
                    mma16816(acc[mi][bj * 2],     a[mi], b0);
                    mma16816(acc[mi][bj * 2 + 1], a[mi], b1);
                }
            }
        }
    }
    // epilogue reads only registers + the vinv region (written pre-loop,
    // ordered by the 8 in-loop barriers) -> no barriers needed here.
    const float* vin = (const float*)(smem + V_OFF);

#pragma unroll
    for (int mi = 0; mi < 2; mi++) {
        float bv0 = -1e30f, bv1 = -1e30f;
        int   bj0 = 0,      bj1 = 0;
#pragma unroll
        for (int nj = 0; nj < 10; nj++) {
            int c0 = warp_n + nj * 8 + 2 * (lane & 3);
            float v00 = acc[mi][nj][0] * vin[c0];
            float v01 = acc[mi][nj][1] * vin[c0 + 1];
            float v10 = acc[mi][nj][2] * vin[c0];
            float v11 = acc[mi][nj][3] * vin[c0 + 1];
            if (v00 > bv0) { bv0 = v00; bj0 = c0; }
            if (v01 > bv0) { bv0 = v01; bj0 = c0 + 1; }
            if (v10 > bv1) { bv1 = v10; bj1 = c0; }
            if (v11 > bv1) { bv1 = v11; bj1 = c0 + 1; }
        }
#pragma unroll
        for (int off = 1; off < 4; off <<= 1) {
            float o0 = __shfl_xor_sync(0xffffffffu, bv0, off);
            int   j0 = __shfl_xor_sync(0xffffffffu, bj0, off);
            float o1 = __shfl_xor_sync(0xffffffffu, bv1, off);
            int   j1 = __shfl_xor_sync(0xffffffffu, bj1, off);
            if (o0 > bv0 || (o0 == bv0 && j0 < bj0)) { bv0 = o0; bj0 = j0; }
            if (o1 > bv1 || (o1 == bv1 && j1 < bj1)) { bv1 = o1; bj1 = j1; }
        }
        if ((lane & 3) == 0) {
            int r0 = mblk + warp_m + mi * 16 + (lane >> 2);
            atomicMax(&g_best[r0],     enc_key(bv0, (unsigned)(nblk + bj0)));
            atomicMax(&g_best[r0 + 8], enc_key(bv1, (unsigned)(nblk + bj1)));
        }
    }
}

// ---------------------------------------------------------------------------
// Kernel 3: per-row hinge (warp/row) + last-block scalar reduction.
// Self-resetting counter keeps the kernel graph-replay safe & deterministic.
// ---------------------------------------------------------------------------
__global__ void __launch_bounds__(256) finalize_reduce_kernel(
        const float* __restrict__ emb,
        const int* __restrict__ target,
        const int* __restrict__ pad,
        float* __restrict__ out) {
    __shared__ int s_last;
    int r    = blockIdx.x * 8 + (threadIdx.x >> 5);
    int lane = threadIdx.x & 31;
    int t = clamp_idx(target[r]);
    unsigned long long key = g_best[r];
    int jm = clamp_idx((int)(0x7fffffffu - (unsigned)(key & 0xffffffffu)));

    const float* on = g_outn + (size_t)r * D_DIM;
    const float* e1 = emb + (size_t)t  * D_DIM;
    const float* e2 = emb + (size_t)jm * D_DIM;
    float d1 = 0.f, d2 = 0.f;
#pragma unroll
    for (int d = lane; d < D_DIM; d += 32) {
        float o = on[d];
        d1 = fmaf(o, e1[d], d1);
        d2 = fmaf(o, e2[d], d2);
    }
#pragma unroll
    for (int off = 16; off; off >>= 1) {
        d1 += __shfl_xor_sync(0xffffffffu, d1, off);
        d2 += __shfl_xor_sync(0xffffffffu, d2, off);
    }
    if (lane == 0) {
        d1 *= g_vinv[t];
        d2 *= g_vinv[jm];
        float df = fmaxf(GAMMA_F + d2 - d1, 0.f);
        g_diff[r] = (target[r] != *pad) ? df : 0.f;
    }
    __threadfence();
    __syncthreads();
    if (threadIdx.x == 0)
        s_last = (atomicAdd(&g_cnt, 1) == (int)gridDim.x - 1) ? 1 : 0;
    __syncthreads();
    if (!s_last) return;

    // last block: deterministic reduction over all 2048 rows
    __shared__ float ssum[256];
    __shared__ float scnt[256];
    int tt = threadIdx.x;
    int p = *pad;
    float s = 0.f, c = 0.f;
    for (int rr = tt; rr < BS_ROWS; rr += 256) {
        s += g_diff[rr];
        c += (target[rr] != p) ? 1.f : 0.f;
    }
    ssum[tt] = s; scnt[tt] = c; __syncthreads();
    for (int off = 128; off; off >>= 1) {
        if (tt < off) { ssum[tt] += ssum[tt + off]; scnt[tt] += scnt[tt + off]; }
        __syncthreads();
    }
    if (tt == 0) {
        out[0] = ssum[0] / scnt[0];
        g_cnt = 0;   // self-reset for next graph replay
    }
}

// ---------------------------------------------------------------------------
extern "C" void kernel_launch(void* const* d_in, const int* in_sizes, int n_in,
                              void* d_out, int out_size) {
    const float* preds  = (const float*)d_in[0];
    const float* emb    = (const float*)d_in[1];
    const int*   target = (const int*)d_in[2];
    const int*   pad    = (const int*)d_in[3];

    cudaFuncSetAttribute(gemm_mma_kernel, cudaFuncAttributeMaxDynamicSharedMemorySize, SMEMSZ);

    pre_kernel<<<VBLKS + 128, 256>>>(emb, preds, target);
    dim3 grid(BS_ROWS / MT, V_DIM / NT);   // (16, 200)
    gemm_mma_kernel<<<grid, 256, SMEMSZ>>>();
    finalize_reduce_kernel<<<BS_ROWS / 8, 256>>>(emb, target, pad, (float*)d_out);
}

// round 11
// speedup vs baseline: 7.6384x; 1.0323x over previous
#include <cuda_runtime.h>
#include <cuda_fp16.h>
#include <math.h>
#include <stdint.h>

// Problem constants
#define D_DIM   512
#define V_DIM   32000
#define BS_ROWS 2048
#define GAMMA_F 0.5f
#define EPS_F   1e-12f

// GEMM tiling: CTA 128x160, 8 warps (warp tile 32x80), 2 CTAs/SM
#define MT 128
#define NT 160
#define KC 64               // fp16 K per chunk (128 B rows)
#define NCHUNK 8            // 512 / 64
#define NSTAGE 3

// SMEM: 128B rows with XOR swizzle (chunk ^= row&7) -> conflict-free ldmatrix
#define ROWB   128
#define A_OFF  0
#define B_OFF  (MT * ROWB)               // 16384
#define STAGE  ((MT + NT) * ROWB)        // 36864
#define V_OFF  (NSTAGE * STAGE)          // 110592 : vinv staging (160 floats)
#define SMEMSZ (V_OFF + NT * 4)          // 111232

// ---------------------------------------------------------------------------
// Static scratch
// ---------------------------------------------------------------------------
__device__ __half g_qh[BS_ROWS * D_DIM];
__device__ __half g_eh[(size_t)V_DIM * D_DIM];
__device__ float              g_vinv[V_DIM];
__device__ float              g_outn[BS_ROWS * D_DIM];
__device__ unsigned long long g_best[BS_ROWS];
__device__ float              g_diff[BS_ROWS];
__device__ int                g_cnt;     // zero-initialized; self-resetting

// ---------------------------------------------------------------------------
// helpers
// ---------------------------------------------------------------------------
__device__ __forceinline__ uint32_t smem_u32(const void* p) {
    uint32_t a;
    asm("{ .reg .u64 t; cvta.to.shared.u64 t, %1; cvt.u32.u64 %0, t; }" : "=r"(a) : "l"(p));
    return a;
}
__device__ __forceinline__ void cp16(uint32_t dst, const void* src) {
    asm volatile("cp.async.cg.shared.global [%0], [%1], 16;" :: "r"(dst), "l"(src));
}
#define CP_COMMIT() asm volatile("cp.async.commit_group;" ::: "memory")
#define CP_WAIT1()  asm volatile("cp.async.wait_group 1;" ::: "memory")
#define CP_WAIT0()  asm volatile("cp.async.wait_group 0;" ::: "memory")

__device__ __forceinline__ void ldsm_x4(uint32_t addr, uint32_t& r0, uint32_t& r1,
                                        uint32_t& r2, uint32_t& r3) {
    asm volatile("ldmatrix.sync.aligned.m8n8.x4.shared.b16 {%0,%1,%2,%3}, [%4];"
                 : "=r"(r0), "=r"(r1), "=r"(r2), "=r"(r3) : "r"(addr));
}
__device__ __forceinline__ void mma16816(float* c, const uint32_t* a, const uint32_t* b) {
    asm volatile(
        "mma.sync.aligned.m16n8k16.row.col.f32.f16.f16.f32 "
        "{%0,%1,%2,%3}, {%4,%5,%6,%7}, {%8,%9}, {%0,%1,%2,%3};"
        : "+f"(c[0]), "+f"(c[1]), "+f"(c[2]), "+f"(c[3])
        : "r"(a[0]), "r"(a[1]), "r"(a[2]), "r"(a[3]), "r"(b[0]), "r"(b[1]));
}

// XOR swizzle: 16B chunk index within a 128B row, xored with row&7
__device__ __forceinline__ uint32_t swz(uint32_t row, uint32_t chunk) {
    return row * ROWB + ((chunk ^ (row & 7u)) << 4);
}

// pack 4 floats -> 4 halves in a uint2 (8B)
__device__ __forceinline__ uint2 pack_h4(float4 v) {
    __half2 lo = __halves2half2(__float2half_rn(v.x), __float2half_rn(v.y));
    __half2 hi = __halves2half2(__float2half_rn(v.z), __float2half_rn(v.w));
    uint2 r;
    r.x = *(uint32_t*)&lo;
    r.y = *(uint32_t*)&hi;
    return r;
}

// Monotone (score, idx) packing; bigger score wins, tie -> smaller index
__device__ __forceinline__ unsigned long long enc_key(float v, unsigned idx) {
    unsigned u = __float_as_uint(v);
    u = (u & 0x80000000u) ? ~u : (u | 0x80000000u);
    return ((unsigned long long)u << 32) | (unsigned long long)(0x7fffffffu - idx);
}
__device__ __forceinline__ int clamp_idx(int t) {
    t = t < 0 ? 0 : t;
    return t >= V_DIM ? V_DIM - 1 : t;
}

// ---------------------------------------------------------------------------
// Kernel 1 (merged): blocks [0,2000) = vocab pass (2 rows per warp, high ILP);
// blocks [2000,2128) = preds transpose + q build (single global pass).
// ---------------------------------------------------------------------------
#define ST 16
#define VBLKS (V_DIM / 16)    // 2000 blocks * 8 warps * 2 rows = 32000
__global__ void __launch_bounds__(256) pre_kernel(const float* __restrict__ emb,
                                                  const float* __restrict__ preds,
                                                  const int* __restrict__ target) {
    __shared__ float tile[D_DIM][ST + 1];   // 34816 B, prep role only
    __shared__ float part[16][17];
    __shared__ float inv_s[ST];
    __shared__ int   tgt_s[ST];

    if (blockIdx.x < VBLKS) {
        // ------- vocab role: each warp handles rows r0, r0+1 -------
        int warp = (blockIdx.x * 256 + threadIdx.x) >> 5;
        int lane = threadIdx.x & 31;
        int r0 = warp * 2;
        const float4* rowA = (const float4*)(emb + (size_t)r0 * D_DIM);
        const float4* rowB = (const float4*)(emb + (size_t)(r0 + 1) * D_DIM);

        float4 va[4], vb[4];
        float sa = 0.f, sb = 0.f;
#pragma unroll
        for (int k = 0; k < 4; k++) {
            va[k] = __ldcs(&rowA[lane + 32 * k]);
            vb[k] = __ldcs(&rowB[lane + 32 * k]);
        }
#pragma unroll
        for (int k = 0; k < 4; k++) {
            sa = fmaf(va[k].x, va[k].x, sa); sa = fmaf(va[k].y, va[k].y, sa);
            sa = fmaf(va[k].z, va[k].z, sa); sa = fmaf(va[k].w, va[k].w, sa);
            sb = fmaf(vb[k].x, vb[k].x, sb); sb = fmaf(vb[k].y, vb[k].y, sb);
            sb = fmaf(vb[k].z, vb[k].z, sb); sb = fmaf(vb[k].w, vb[k].w, sb);
        }
#pragma unroll
        for (int off = 16; off; off >>= 1) {
            sa += __shfl_xor_sync(0xffffffffu, sa, off);
            sb += __shfl_xor_sync(0xffffffffu, sb, off);
        }
        if (lane == 0) {
            g_vinv[r0]     = 1.f / fmaxf(sqrtf(sa), EPS_F);
            g_vinv[r0 + 1] = 1.f / fmaxf(sqrtf(sb), EPS_F);
        }
#pragma unroll
        for (int k = 0; k < 4; k++) {
            size_t ea = (size_t)r0 * D_DIM + (lane + 32 * k) * 4;
            *(uint2*)(g_eh + ea)         = pack_h4(va[k]);
            *(uint2*)(g_eh + ea + D_DIM) = pack_h4(vb[k]);
        }
        return;
    }

    // ------- prep role: single global pass, smem-staged transpose -------
    int blk = blockIdx.x - VBLKS;       // 0..127
    int b   = blk >> 5;                 // 4 batches x 32 s-tiles
    int s0  = (blk & 31) * ST;
    int t   = threadIdx.x;
    const float* P = preds + (size_t)b * D_DIM * 512 + s0;

    // stage the full [512 d x 16 s] tile (each thread 32 elements)
    int ss = t & 15, dr = t >> 4;
#pragma unroll 8
    for (int d0 = 0; d0 < D_DIM; d0 += 16)
        tile[d0 + dr][ss] = P[(size_t)(d0 + dr) * 512 + ss];
    __syncthreads();

    // norms from smem
    float acc = 0.f;
#pragma unroll 8
    for (int d0 = 0; d0 < D_DIM; d0 += 16)
        { float x = tile[d0 + dr][ss]; acc = fmaf(x, x, acc); }
    part[dr][ss] = acc;
    __syncthreads();
    if (t < ST) {
        float n = 0.f;
#pragma unroll
        for (int i = 0; i < 16; i++) n += part[i][t];
        inv_s[t] = 1.f / fmaxf(sqrtf(n), EPS_F);
        int r = b * 512 + s0 + t;
        tgt_s[t] = clamp_idx(target[r]);
        g_best[r] = 0ull;
    }
    __syncthreads();

    // transposed writes: thread -> (seq row ss2, 4 consecutive d)
    int ss2  = t >> 4;
    int dcol = (t & 15) * 4;
    float inv = inv_s[ss2];
    int r = b * 512 + s0 + ss2;
    const float* erow = emb + (size_t)tgt_s[ss2] * D_DIM;
#pragma unroll
    for (int d0 = 0; d0 < D_DIM; d0 += 64) {
        float4 o;
        __half hq[4];
        float* ov = &o.x;
#pragma unroll
        for (int j = 0; j < 4; j++) {
            float on = tile[d0 + dcol + j][ss2] * inv;
            ov[j] = on;
            hq[j] = __float2half_rn(on - erow[d0 + dcol + j]);
        }
        *(float4*)(g_outn + (size_t)r * D_DIM + d0 + dcol) = o;
        *(__half2*)(g_qh + (size_t)r * D_DIM + d0 + dcol)     = __halves2half2(hq[0], hq[1]);
        *(__half2*)(g_qh + (size_t)r * D_DIM + d0 + dcol + 2) = __halves2half2(hq[2], hq[3]);
    }
}

// ---------------------------------------------------------------------------
// Kernel 2: fp16 mma.sync GEMM, 3-stage cp.async (1 barrier/chunk), 2 CTAs/SM,
// XOR-swizzled SMEM, vinv prefetched pre-loop, fused argmax epilogue.
// CTA 128x160, warp tile 32x80.
// ---------------------------------------------------------------------------
__global__ void __launch_bounds__(256, 2) gemm_mma_kernel() {
    extern __shared__ char smem[];
    const uint32_t sb = smem_u32(smem);
    const int tid  = threadIdx.x;
    const int wid  = tid >> 5;
    const int lane = tid & 31;
    const int mblk = blockIdx.x * MT;
    const int nblk = blockIdx.y * NT;
    const int warp_m = (wid & 3) * 32;      // 4 warps along M
    const int warp_n = (wid >> 2) * 80;     // 2 warps along N

    const __half* Aqh = g_qh + (size_t)mblk * D_DIM;
    const __half* Beh = g_eh + (size_t)nblk * D_DIM;

    if (tid < NT) ((float*)(smem + V_OFF))[tid] = g_vinv[nblk + tid];

    auto load_chunk = [&](int slot, int ch) {
        int kc = ch * KC;
        uint32_t st = sb + slot * STAGE;
#pragma unroll
        for (int i = 0; i < 4; i++) {
            int s = tid + i * 256;
            int row = s >> 3, c = s & 7;
            cp16(st + A_OFF + swz(row, c), Aqh + (size_t)row * D_DIM + kc + c * 8);
        }
#pragma unroll
        for (int i = 0; i < 5; i++) {
            int s = tid + i * 256;
            int row = s >> 3, c = s & 7;
            cp16(st + B_OFF + swz(row, c), Beh + (size_t)row * D_DIM + kc + c * 8);
        }
    };

    float acc[2][10][4];
#pragma unroll
    for (int i = 0; i < 2; i++)
#pragma unroll
        for (int j = 0; j < 10; j++)
#pragma unroll
            for (int k = 0; k < 4; k++) acc[i][j][k] = 0.f;

    load_chunk(0, 0); CP_COMMIT();
    load_chunk(1, 1); CP_COMMIT();

    for (int it = 0; it < NCHUNK; it++) {
        if (it + 1 < NCHUNK) { CP_WAIT1(); } else { CP_WAIT0(); }
        __syncthreads();

        if (it + 2 < NCHUNK) {
            load_chunk((it + 2) % NSTAGE, it + 2);
            CP_COMMIT();
        }

        uint32_t st  = sb + (it % NSTAGE) * STAGE;
        uint32_t sa  = st + A_OFF;
        uint32_t sbm = st + B_OFF;
#pragma unroll
        for (int ks = 0; ks < 4; ks++) {
            int k = ks * 16;
            uint32_t a[2][4];
#pragma unroll
            for (int mi = 0; mi < 2; mi++) {
                int row = warp_m + mi * 16 + (lane & 15);
                int kch = (k >> 3) + (lane >> 4);
                ldsm_x4(sa + swz(row, kch), a[mi][0], a[mi][1], a[mi][2], a[mi][3]);
            }
#pragma unroll
            for (int bj = 0; bj < 5; bj++) {
                uint32_t b0[2], b1[2];
                int n   = warp_n + bj * 16 + (lane & 7) + ((lane >> 4) & 1) * 8;
                int kch = (k >> 3) + ((lane >> 3) & 1);
                ldsm_x4(sbm + swz(n, kch), b0[0], b0[1], b1[0], b1[1]);
#pragma unroll
                for (int mi = 0; mi < 2; mi++) {
                    mma16816(acc[mi][bj * 2],     a[mi], b0);
                    mma16816(acc[mi][bj * 2 + 1], a[mi], b1);
                }
            }
        }
    }
    const float* vin = (const float*)(smem + V_OFF);

#pragma unroll
    for (int mi = 0; mi < 2; mi++) {
        float bv0 = -1e30f, bv1 = -1e30f;
        int   bj0 = 0,      bj1 = 0;
#pragma unroll
        for (int nj = 0; nj < 10; nj++) {
            int c0 = warp_n + nj * 8 + 2 * (lane & 3);
            float v00 = acc[mi][nj][0] * vin[c0];
            float v01 = acc[mi][nj][1] * vin[c0 + 1];
            float v10 = acc[mi][nj][2] * vin[c0];
            float v11 = acc[mi][nj][3] * vin[c0 + 1];
            if (v00 > bv0) { bv0 = v00; bj0 = c0; }
            if (v01 > bv0) { bv0 = v01; bj0 = c0 + 1; }
            if (v10 > bv1) { bv1 = v10; bj1 = c0; }
            if (v11 > bv1) { bv1 = v11; bj1 = c0 + 1; }
        }
#pragma unroll
        for (int off = 1; off < 4; off <<= 1) {
            float o0 = __shfl_xor_sync(0xffffffffu, bv0, off);
            int   j0 = __shfl_xor_sync(0xffffffffu, bj0, off);
            float o1 = __shfl_xor_sync(0xffffffffu, bv1, off);
            int   j1 = __shfl_xor_sync(0xffffffffu, bj1, off);
            if (o0 > bv0 || (o0 == bv0 && j0 < bj0)) { bv0 = o0; bj0 = j0; }
            if (o1 > bv1 || (o1 == bv1 && j1 < bj1)) { bv1 = o1; bj1 = j1; }
        }
        if ((lane & 3) == 0) {
            int r0 = mblk + warp_m + mi * 16 + (lane >> 2);
            atomicMax(&g_best[r0],     enc_key(bv0, (unsigned)(nblk + bj0)));
            atomicMax(&g_best[r0 + 8], enc_key(bv1, (unsigned)(nblk + bj1)));
        }
    }
}

// ---------------------------------------------------------------------------
// Kernel 3: per-row hinge (warp/row) + last-block scalar reduction.
// ---------------------------------------------------------------------------
__global__ void __launch_bounds__(256) finalize_reduce_kernel(
        const float* __restrict__ emb,
        const int* __restrict__ target,
        const int* __restrict__ pad,
        float* __restrict__ out) {
    __shared__ int s_last;
    int r    = blockIdx.x * 8 + (threadIdx.x >> 5);
    int lane = threadIdx.x & 31;
    int t = clamp_idx(target[r]);
    unsigned long long key = g_best[r];
    int jm = clamp_idx((int)(0x7fffffffu - (unsigned)(key & 0xffffffffu)));

    const float* on = g_outn + (size_t)r * D_DIM;
    const float* e1 = emb + (size_t)t  * D_DIM;
    const float* e2 = emb + (size_t)jm * D_DIM;
    float d1 = 0.f, d2 = 0.f;
#pragma unroll
    for (int d = lane; d < D_DIM; d += 32) {
        float o = on[d];
        d1 = fmaf(o, e1[d], d1);
        d2 = fmaf(o, e2[d], d2);
    }
#pragma unroll
    for (int off = 16; off; off >>= 1) {
        d1 += __shfl_xor_sync(0xffffffffu, d1, off);
        d2 += __shfl_xor_sync(0xffffffffu, d2, off);
    }
    if (lane == 0) {
        d1 *= g_vinv[t];
        d2 *= g_vinv[jm];
        float df = fmaxf(GAMMA_F + d2 - d1, 0.f);
        g_diff[r] = (target[r] != *pad) ? df : 0.f;
    }
    __threadfence();
    __syncthreads();
    if (threadIdx.x == 0)
        s_last = (atomicAdd(&g_cnt, 1) == (int)gridDim.x - 1) ? 1 : 0;
    __syncthreads();
    if (!s_last) return;

    __shared__ float ssum[256];
    __shared__ float scnt[256];
    int tt = threadIdx.x;
    int p = *pad;
    float s = 0.f, c = 0.f;
    for (int rr = tt; rr < BS_ROWS; rr += 256) {
        s += g_diff[rr];
        c += (target[rr] != p) ? 1.f : 0.f;
    }
    ssum[tt] = s; scnt[tt] = c; __syncthreads();
    for (int off = 128; off; off >>= 1) {
        if (tt < off) { ssum[tt] += ssum[tt + off]; scnt[tt] += scnt[tt + off]; }
        __syncthreads();
    }
    if (tt == 0) {
        out[0] = ssum[0] / scnt[0];
        g_cnt = 0;   // self-reset for next graph replay
    }
}

// ---------------------------------------------------------------------------
extern "C" void kernel_launch(void* const* d_in, const int* in_sizes, int n_in,
                              void* d_out, int out_size) {
    const float* preds  = (const float*)d_in[0];
    const float* emb    = (const float*)d_in[1];
    const int*   target = (const int*)d_in[2];
    const int*   pad    = (const int*)d_in[3];

    cudaFuncSetAttribute(gemm_mma_kernel, cudaFuncAttributeMaxDynamicSharedMemorySize, SMEMSZ);

    pre_kernel<<<VBLKS + 128, 256>>>(emb, preds, target);
    dim3 grid(BS_ROWS / MT, V_DIM / NT);   // (16, 200)
    gemm_mma_kernel<<<grid, 256, SMEMSZ>>>();
    finalize_reduce_kernel<<<BS_ROWS / 8, 256>>>(emb, target, pad, (float*)d_out);
}

// round 12
// speedup vs baseline: 7.7516x; 1.0148x over previous
#include <cuda_runtime.h>
#include <cuda_fp16.h>
#include <math.h>
#include <stdint.h>

// Problem constants
#define D_DIM   512
#define V_DIM   32000
#define BS_ROWS 2048
#define GAMMA_F 0.5f
#define EPS_F   1e-12f

// GEMM tiling: CTA 128x160, 8 warps (warp tile 32x80), 2 CTAs/SM
#define MT 128
#define NT 160
#define KC 64               // fp16 K per chunk (128 B rows)
#define NCHUNK 8            // 512 / 64
#define NSTAGE 3

// SMEM: 128B rows with XOR swizzle (chunk ^= row&7) -> conflict-free ldmatrix
#define ROWB   128
#define A_OFF  0
#define B_OFF  (MT * ROWB)               // 16384
#define STAGE  ((MT + NT) * ROWB)        // 36864
#define V_OFF  (NSTAGE * STAGE)          // 110592 : vinv staging (160 floats)
#define SMEMSZ (V_OFF + NT * 4)          // 111232

// ---------------------------------------------------------------------------
// Static scratch
// ---------------------------------------------------------------------------
__device__ __half g_qh[BS_ROWS * D_DIM];
__device__ __half g_eh[(size_t)V_DIM * D_DIM];
__device__ float              g_vinv[V_DIM];
__device__ float              g_outn[BS_ROWS * D_DIM];
__device__ unsigned long long g_best[BS_ROWS];
__device__ float              g_diff[BS_ROWS];
__device__ int                g_cnt;     // zero-initialized; self-resetting

// ---------------------------------------------------------------------------
// helpers
// ---------------------------------------------------------------------------
__device__ __forceinline__ uint32_t smem_u32(const void* p) {
    uint32_t a;
    asm("{ .reg .u64 t; cvta.to.shared.u64 t, %1; cvt.u32.u64 %0, t; }" : "=r"(a) : "l"(p));
    return a;
}
__device__ __forceinline__ void cp16(uint32_t dst, const void* src) {
    asm volatile("cp.async.cg.shared.global [%0], [%1], 16;" :: "r"(dst), "l"(src));
}
#define CP_COMMIT() asm volatile("cp.async.commit_group;" ::: "memory")
#define CP_WAIT1()  asm volatile("cp.async.wait_group 1;" ::: "memory")
#define CP_WAIT0()  asm volatile("cp.async.wait_group 0;" ::: "memory")

__device__ __forceinline__ void ldsm_x4(uint32_t addr, uint32_t& r0, uint32_t& r1,
                                        uint32_t& r2, uint32_t& r3) {
    asm volatile("ldmatrix.sync.aligned.m8n8.x4.shared.b16 {%0,%1,%2,%3}, [%4];"
                 : "=r"(r0), "=r"(r1), "=r"(r2), "=r"(r3) : "r"(addr));
}
__device__ __forceinline__ void mma16816(float* c, const uint32_t* a, const uint32_t* b) {
    asm volatile(
        "mma.sync.aligned.m16n8k16.row.col.f32.f16.f16.f32 "
        "{%0,%1,%2,%3}, {%4,%5,%6,%7}, {%8,%9}, {%0,%1,%2,%3};"
        : "+f"(c[0]), "+f"(c[1]), "+f"(c[2]), "+f"(c[3])
        : "r"(a[0]), "r"(a[1]), "r"(a[2]), "r"(a[3]), "r"(b[0]), "r"(b[1]));
}

// XOR swizzle: 16B chunk index within a 128B row, xored with row&7
__device__ __forceinline__ uint32_t swz(uint32_t row, uint32_t chunk) {
    return row * ROWB + ((chunk ^ (row & 7u)) << 4);
}

// pack 4 floats -> 4 halves in a uint2 (8B)
__device__ __forceinline__ uint2 pack_h4(float4 v) {
    __half2 lo = __halves2half2(__float2half_rn(v.x), __float2half_rn(v.y));
    __half2 hi = __halves2half2(__float2half_rn(v.z), __float2half_rn(v.w));
    uint2 r;
    r.x = *(uint32_t*)&lo;
    r.y = *(uint32_t*)&hi;
    return r;
}

// Monotone (score, idx) packing; bigger score wins, tie -> smaller index
__device__ __forceinline__ unsigned long long enc_key(float v, unsigned idx) {
    unsigned u = __float_as_uint(v);
    u = (u & 0x80000000u) ? ~u : (u | 0x80000000u);
    return ((unsigned long long)u << 32) | (unsigned long long)(0x7fffffffu - idx);
}
__device__ __forceinline__ int clamp_idx(int t) {
    t = t < 0 ? 0 : t;
    return t >= V_DIM ? V_DIM - 1 : t;
}

// ---------------------------------------------------------------------------
// Kernel 1 (merged): blocks [0,2000) = vocab pass (2 rows per warp, high ILP);
// blocks [2000,2256) = preds transpose + q build (single global pass, ST=8
// keeps static smem ~20KB so vocab blocks can pack ~11/SM).
// ---------------------------------------------------------------------------
#define ST 8
#define VBLKS (V_DIM / 16)    // 2000 blocks * 8 warps * 2 rows = 32000
#define PBLKS (BS_ROWS / ST)  // 256
__global__ void __launch_bounds__(256) pre_kernel(const float* __restrict__ emb,
                                                  const float* __restrict__ preds,
                                                  const int* __restrict__ target) {
    __shared__ float tile[D_DIM][ST + 1];   // 18432 B, prep role only
    __shared__ float part[32][ST + 1];
    __shared__ float inv_s[ST];
    __shared__ int   tgt_s[ST];

    if (blockIdx.x < VBLKS) {
        // ------- vocab role: each warp handles rows r0, r0+1 -------
        int warp = (blockIdx.x * 256 + threadIdx.x) >> 5;
        int lane = threadIdx.x & 31;
        int r0 = warp * 2;
        const float4* rowA = (const float4*)(emb + (size_t)r0 * D_DIM);
        const float4* rowB = (const float4*)(emb + (size_t)(r0 + 1) * D_DIM);

        float4 va[4], vb[4];
        float sa = 0.f, sb = 0.f;
#pragma unroll
        for (int k = 0; k < 4; k++) {
            va[k] = __ldcs(&rowA[lane + 32 * k]);
            vb[k] = __ldcs(&rowB[lane + 32 * k]);
        }
#pragma unroll
        for (int k = 0; k < 4; k++) {
            sa = fmaf(va[k].x, va[k].x, sa); sa = fmaf(va[k].y, va[k].y, sa);
            sa = fmaf(va[k].z, va[k].z, sa); sa = fmaf(va[k].w, va[k].w, sa);
            sb = fmaf(vb[k].x, vb[k].x, sb); sb = fmaf(vb[k].y, vb[k].y, sb);
            sb = fmaf(vb[k].z, vb[k].z, sb); sb = fmaf(vb[k].w, vb[k].w, sb);
        }
#pragma unroll
        for (int off = 16; off; off >>= 1) {
            sa += __shfl_xor_sync(0xffffffffu, sa, off);
            sb += __shfl_xor_sync(0xffffffffu, sb, off);
        }
        if (lane == 0) {
            g_vinv[r0]     = 1.f / fmaxf(sqrtf(sa), EPS_F);
            g_vinv[r0 + 1] = 1.f / fmaxf(sqrtf(sb), EPS_F);
        }
#pragma unroll
        for (int k = 0; k < 4; k++) {
            size_t ea = (size_t)r0 * D_DIM + (lane + 32 * k) * 4;
            *(uint2*)(g_eh + ea)         = pack_h4(va[k]);
            *(uint2*)(g_eh + ea + D_DIM) = pack_h4(vb[k]);
        }
        return;
    }

    // ------- prep role: single global pass, smem-staged transpose -------
    int blk = blockIdx.x - VBLKS;       // 0..255
    int b   = blk >> 6;                 // 4 batches x 64 s-tiles
    int s0  = (blk & 63) * ST;
    int t   = threadIdx.x;
    const float* P = preds + (size_t)b * D_DIM * 512 + s0;

    // stage the full [512 d x 8 s] tile (each thread 16 elements)
    int ss = t & 7, dr = t >> 3;        // ss 0..7, dr 0..31
#pragma unroll
    for (int d0 = 0; d0 < D_DIM; d0 += 32)
        tile[d0 + dr][ss] = P[(size_t)(d0 + dr) * 512 + ss];
    __syncthreads();

    // norms from smem
    float acc = 0.f;
#pragma unroll
    for (int d0 = 0; d0 < D_DIM; d0 += 32)
        { float x = tile[d0 + dr][ss]; acc = fmaf(x, x, acc); }
    part[dr][ss] = acc;
    __syncthreads();
    if (t < ST) {
        float n = 0.f;
#pragma unroll
        for (int i = 0; i < 32; i++) n += part[i][t];
        inv_s[t] = 1.f / fmaxf(sqrtf(n), EPS_F);
        int r = b * 512 + s0 + t;
        tgt_s[t] = clamp_idx(target[r]);
        g_best[r] = 0ull;
    }
    __syncthreads();

    // transposed writes: thread -> (seq row ss2, 4 consecutive d)
    int ss2  = t >> 5;                  // 0..7 (warp id)
    int dcol = (t & 31) * 4;            // 0..124 step 4
    float inv = inv_s[ss2];
    int r = b * 512 + s0 + ss2;
    const float* erow = emb + (size_t)tgt_s[ss2] * D_DIM;
#pragma unroll
    for (int d0 = 0; d0 < D_DIM; d0 += 128) {
        float4 o;
        __half hq[4];
        float* ov = &o.x;
#pragma unroll
        for (int j = 0; j < 4; j++) {
            float on = tile[d0 + dcol + j][ss2] * inv;
            ov[j] = on;
            hq[j] = __float2half_rn(on - erow[d0 + dcol + j]);
        }
        *(float4*)(g_outn + (size_t)r * D_DIM + d0 + dcol) = o;
        *(__half2*)(g_qh + (size_t)r * D_DIM + d0 + dcol)     = __halves2half2(hq[0], hq[1]);
        *(__half2*)(g_qh + (size_t)r * D_DIM + d0 + dcol + 2) = __halves2half2(hq[2], hq[3]);
    }
}

// ---------------------------------------------------------------------------
// Kernel 2: fp16 mma.sync GEMM, 3-stage cp.async (1 barrier/chunk), 2 CTAs/SM,
// XOR-swizzled SMEM, vinv prefetched pre-loop, fused argmax epilogue.
// CTA 128x160, warp tile 32x80.
// ---------------------------------------------------------------------------
__global__ void __launch_bounds__(256, 2) gemm_mma_kernel() {
    extern __shared__ char smem[];
    const uint32_t sb = smem_u32(smem);
    const int tid  = threadIdx.x;
    const int wid  = tid >> 5;
    const int lane = tid & 31;
    const int mblk = blockIdx.x * MT;
    const int nblk = blockIdx.y * NT;
    const int warp_m = (wid & 3) * 32;      // 4 warps along M
    const int warp_n = (wid >> 2) * 80;     // 2 warps along N

    const __half* Aqh = g_qh + (size_t)mblk * D_DIM;
    const __half* Beh = g_eh + (size_t)nblk * D_DIM;

    if (tid < NT) ((float*)(smem + V_OFF))[tid] = g_vinv[nblk + tid];

    auto load_chunk = [&](int slot, int ch) {
        int kc = ch * KC;
        uint32_t st = sb + slot * STAGE;
#pragma unroll
        for (int i = 0; i < 4; i++) {
            int s = tid + i * 256;
            int row = s >> 3, c = s & 7;
            cp16(st + A_OFF + swz(row, c), Aqh + (size_t)row * D_DIM + kc + c * 8);
        }
#pragma unroll
        for (int i = 0; i < 5; i++) {
            int s = tid + i * 256;
            int row = s >> 3, c = s & 7;
            cp16(st + B_OFF + swz(row, c), Beh + (size_t)row * D_DIM + kc + c * 8);
        }
    };

    float acc[2][10][4];
#pragma unroll
    for (int i = 0; i < 2; i++)
#pragma unroll
        for (int j = 0; j < 10; j++)
#pragma unroll
            for (int k = 0; k < 4; k++) acc[i][j][k] = 0.f;

    load_chunk(0, 0); CP_COMMIT();
    load_chunk(1, 1); CP_COMMIT();

    for (int it = 0; it < NCHUNK; it++) {
        if (it + 1 < NCHUNK) { CP_WAIT1(); } else { CP_WAIT0(); }
        __syncthreads();

        if (it + 2 < NCHUNK) {
            load_chunk((it + 2) % NSTAGE, it + 2);
            CP_COMMIT();
        }

        uint32_t st  = sb + (it % NSTAGE) * STAGE;
        uint32_t sa  = st + A_OFF;
        uint32_t sbm = st + B_OFF;
#pragma unroll
        for (int ks = 0; ks < 4; ks++) {
            int k = ks * 16;
            uint32_t a[2][4];
#pragma unroll
            for (int mi = 0; mi < 2; mi++) {
                int row = warp_m + mi * 16 + (lane & 15);
                int kch = (k >> 3) + (lane >> 4);
                ldsm_x4(sa + swz(row, kch), a[mi][0], a[mi][1], a[mi][2], a[mi][3]);
            }
#pragma unroll
            for (int bj = 0; bj < 5; bj++) {
                uint32_t b0[2], b1[2];
                int n   = warp_n + bj * 16 + (lane & 7) + ((lane >> 4) & 1) * 8;
                int kch = (k >> 3) + ((lane >> 3) & 1);
                ldsm_x4(sbm + swz(n, kch), b0[0], b0[1], b1[0], b1[1]);
#pragma unroll
                for (int mi = 0; mi < 2; mi++) {
                    mma16816(acc[mi][bj * 2],     a[mi], b0);
                    mma16816(acc[mi][bj * 2 + 1], a[mi], b1);
                }
            }
        }
    }
    const float* vin = (const float*)(smem + V_OFF);

#pragma unroll
    for (int mi = 0; mi < 2; mi++) {
        float bv0 = -1e30f, bv1 = -1e30f;
        int   bj0 = 0,      bj1 = 0;
#pragma unroll
        for (int nj = 0; nj < 10; nj++) {
            int c0 = warp_n + nj * 8 + 2 * (lane & 3);
            float v00 = acc[mi][nj][0] * vin[c0];
            float v01 = acc[mi][nj][1] * vin[c0 + 1];
            float v10 = acc[mi][nj][2] * vin[c0];
            float v11 = acc[mi][nj][3] * vin[c0 + 1];
            if (v00 > bv0) { bv0 = v00; bj0 = c0; }
            if (v01 > bv0) { bv0 = v01; bj0 = c0 + 1; }
            if (v10 > bv1) { bv1 = v10; bj1 = c0; }
            if (v11 > bv1) { bv1 = v11; bj1 = c0 + 1; }
        }
#pragma unroll
        for (int off = 1; off < 4; off <<= 1) {
            float o0 = __shfl_xor_sync(0xffffffffu, bv0, off);
            int   j0 = __shfl_xor_sync(0xffffffffu, bj0, off);
            float o1 = __shfl_xor_sync(0xffffffffu, bv1, off);
            int   j1 = __shfl_xor_sync(0xffffffffu, bj1, off);
            if (o0 > bv0 || (o0 == bv0 && j0 < bj0)) { bv0 = o0; bj0 = j0; }
            if (o1 > bv1 || (o1 == bv1 && j1 < bj1)) { bv1 = o1; bj1 = j1; }
        }
        if ((lane & 3) == 0) {
            int r0 = mblk + warp_m + mi * 16 + (lane >> 2);
            atomicMax(&g_best[r0],     enc_key(bv0, (unsigned)(nblk + bj0)));
            atomicMax(&g_best[r0 + 8], enc_key(bv1, (unsigned)(nblk + bj1)));
        }
    }
}

// ---------------------------------------------------------------------------
// Kernel 3: per-row hinge (warp/row, float4 gathers) + last-block reduction.
// ---------------------------------------------------------------------------
__global__ void __launch_bounds__(256) finalize_reduce_kernel(
        const float* __restrict__ emb,
        const int* __restrict__ target,
        const int* __restrict__ pad,
        float* __restrict__ out) {
    __shared__ int s_last;
    int r    = blockIdx.x * 8 + (threadIdx.x >> 5);
    int lane = threadIdx.x & 31;
    int t = clamp_idx(target[r]);
    unsigned long long key = g_best[r];
    int jm = clamp_idx((int)(0x7fffffffu - (unsigned)(key & 0xffffffffu)));

    const float4* on = (const float4*)(g_outn + (size_t)r * D_DIM);
    const float4* e1 = (const float4*)(emb + (size_t)t  * D_DIM);
    const float4* e2 = (const float4*)(emb + (size_t)jm * D_DIM);
    float d1 = 0.f, d2 = 0.f;
#pragma unroll
    for (int i = 0; i < 4; i++) {
        int idx = lane + i * 32;
        float4 o = on[idx], a = e1[idx], b2 = e2[idx];
        d1 = fmaf(o.x, a.x, d1);  d1 = fmaf(o.y, a.y, d1);
        d1 = fmaf(o.z, a.z, d1);  d1 = fmaf(o.w, a.w, d1);
        d2 = fmaf(o.x, b2.x, d2); d2 = fmaf(o.y, b2.y, d2);
        d2 = fmaf(o.z, b2.z, d2); d2 = fmaf(o.w, b2.w, d2);
    }
#pragma unroll
    for (int off = 16; off; off >>= 1) {
        d1 += __shfl_xor_sync(0xffffffffu, d1, off);
        d2 += __shfl_xor_sync(0xffffffffu, d2, off);
    }
    if (lane == 0) {
        d1 *= g_vinv[t];
        d2 *= g_vinv[jm];
        float df = fmaxf(GAMMA_F + d2 - d1, 0.f);
        g_diff[r] = (target[r] != *pad) ? df : 0.f;
    }
    __threadfence();
    __syncthreads();
    if (threadIdx.x == 0)
        s_last = (atomicAdd(&g_cnt, 1) == (int)gridDim.x - 1) ? 1 : 0;
    __syncthreads();
    if (!s_last) return;

    __shared__ float ssum[256];
    __shared__ float scnt[256];
    int tt = threadIdx.x;
    int p = *pad;
    float s = 0.f, c = 0.f;
    for (int rr = tt; rr < BS_ROWS; rr += 256) {
        s += g_diff[rr];
        c += (target[rr] != p) ? 1.f : 0.f;
    }
    ssum[tt] = s; scnt[tt] = c; __syncthreads();
    for (int off = 128; off; off >>= 1) {
        if (tt < off) { ssum[tt] += ssum[tt + off]; scnt[tt] += scnt[tt + off]; }
        __syncthreads();
    }
    if (tt == 0) {
        out[0] = ssum[0] / scnt[0];
        g_cnt = 0;   // self-reset for next graph replay
    }
}

// ---------------------------------------------------------------------------
extern "C" void kernel_launch(void* const* d_in, const int* in_sizes, int n_in,
                              void* d_out, int out_size) {
    const float* preds  = (const float*)d_in[0];
    const float* emb    = (const float*)d_in[1];
    const int*   target = (const int*)d_in[2];
    const int*   pad    = (const int*)d_in[3];

    cudaFuncSetAttribute(gemm_mma_kernel, cudaFuncAttributeMaxDynamicSharedMemorySize, SMEMSZ);

    pre_kernel<<<VBLKS + PBLKS, 256>>>(emb, preds, target);
    dim3 grid(BS_ROWS / MT, V_DIM / NT);   // (16, 200)
    gemm_mma_kernel<<<grid, 256, SMEMSZ>>>();
    finalize_reduce_kernel<<<BS_ROWS / 8, 256>>>(emb, target, pad, (float*)d_out);
}

// round 13
// speedup vs baseline: 7.7797x; 1.0036x over previous
#include <cuda_runtime.h>
#include <cuda_fp16.h>
#include <math.h>
#include <stdint.h>

// Problem constants
#define D_DIM   512
#define V_DIM   32000
#define BS_ROWS 2048
#define GAMMA_F 0.5f
#define EPS_F   1e-12f

// GEMM tiling: CTA 128x160, 8 warps (warp tile 32x80), 2 CTAs/SM
#define MT 128
#define NT 160
#define KC 64               // fp16 K per chunk (128 B rows)
#define NCHUNK 8            // 512 / 64
#define NSTAGE 3

// SMEM: 128B rows with XOR swizzle (chunk ^= row&7) -> conflict-free ldmatrix
#define ROWB   128
#define A_OFF  0
#define B_OFF  (MT * ROWB)               // 16384
#define STAGE  ((MT + NT) * ROWB)        // 36864
#define V_OFF  (NSTAGE * STAGE)          // 110592 : vinv staging (160 floats)
#define SMEMSZ (V_OFF + NT * 4)          // 111232

// ---------------------------------------------------------------------------
// Static scratch
// ---------------------------------------------------------------------------
__device__ __half g_qh[BS_ROWS * D_DIM];
__device__ __half g_eh[(size_t)V_DIM * D_DIM];
__device__ float              g_vinv[V_DIM];
__device__ float              g_outn[BS_ROWS * D_DIM];
__device__ unsigned long long g_best[BS_ROWS];
__device__ float              g_diff[BS_ROWS];
__device__ int                g_cnt;     // zero-initialized; self-resetting

// ---------------------------------------------------------------------------
// helpers
// ---------------------------------------------------------------------------
__device__ __forceinline__ uint32_t smem_u32(const void* p) {
    uint32_t a;
    asm("{ .reg .u64 t; cvta.to.shared.u64 t, %1; cvt.u32.u64 %0, t; }" : "=r"(a) : "l"(p));
    return a;
}
__device__ __forceinline__ void cp16(uint32_t dst, const void* src) {
    asm volatile("cp.async.cg.shared.global [%0], [%1], 16;" :: "r"(dst), "l"(src));
}
#define CP_COMMIT() asm volatile("cp.async.commit_group;" ::: "memory")
#define CP_WAIT1()  asm volatile("cp.async.wait_group 1;" ::: "memory")
#define CP_WAIT0()  asm volatile("cp.async.wait_group 0;" ::: "memory")

__device__ __forceinline__ void ldsm_x4(uint32_t addr, uint32_t& r0, uint32_t& r1,
                                        uint32_t& r2, uint32_t& r3) {
    asm volatile("ldmatrix.sync.aligned.m8n8.x4.shared.b16 {%0,%1,%2,%3}, [%4];"
                 : "=r"(r0), "=r"(r1), "=r"(r2), "=r"(r3) : "r"(addr));
}
__device__ __forceinline__ void mma16816(float* c, const uint32_t* a, const uint32_t* b) {
    asm volatile(
        "mma.sync.aligned.m16n8k16.row.col.f32.f16.f16.f32 "
        "{%0,%1,%2,%3}, {%4,%5,%6,%7}, {%8,%9}, {%0,%1,%2,%3};"
        : "+f"(c[0]), "+f"(c[1]), "+f"(c[2]), "+f"(c[3])
        : "r"(a[0]), "r"(a[1]), "r"(a[2]), "r"(a[3]), "r"(b[0]), "r"(b[1]));
}

// XOR swizzle: 16B chunk index within a 128B row, xored with row&7
__device__ __forceinline__ uint32_t swz(uint32_t row, uint32_t chunk) {
    return row * ROWB + ((chunk ^ (row & 7u)) << 4);
}

// pack 4 floats -> 4 halves in a uint2 (8B)
__device__ __forceinline__ uint2 pack_h4(float4 v) {
    __half2 lo = __halves2half2(__float2half_rn(v.x), __float2half_rn(v.y));
    __half2 hi = __halves2half2(__float2half_rn(v.z), __float2half_rn(v.w));
    uint2 r;
    r.x = *(uint32_t*)&lo;
    r.y = *(uint32_t*)&hi;
    return r;
}

// Monotone (score, idx) packing; bigger score wins, tie -> smaller index
__device__ __forceinline__ unsigned long long enc_key(float v, unsigned idx) {
    unsigned u = __float_as_uint(v);
    u = (u & 0x80000000u) ? ~u : (u | 0x80000000u);
    return ((unsigned long long)u << 32) | (unsigned long long)(0x7fffffffu - idx);
}
__device__ __forceinline__ int clamp_idx(int t) {
    t = t < 0 ? 0 : t;
    return t >= V_DIM ? V_DIM - 1 : t;
}

// ---------------------------------------------------------------------------
// Kernel 1 (merged): blocks [0,2000) = vocab pass (2 rows per warp);
// blocks [2000,2512) = preds transpose + q build (ST=4, ~11KB smem).
// launch_bounds(256,6) caps regs at 42 -> 6 blocks/SM.
// ---------------------------------------------------------------------------
#define ST 4
#define VBLKS (V_DIM / 16)    // 2000 blocks * 8 warps * 2 rows = 32000
#define PBLKS (BS_ROWS / ST)  // 512
__global__ void __launch_bounds__(256, 6) pre_kernel(const float* __restrict__ emb,
                                                     const float* __restrict__ preds,
                                                     const int* __restrict__ target) {
    __shared__ float tile[D_DIM][ST + 1];   // 10240 B, prep role only
    __shared__ float part[64][ST + 1];
    __shared__ float inv_s[ST];
    __shared__ int   tgt_s[ST];

    if (blockIdx.x < VBLKS) {
        // ------- vocab role: each warp handles rows r0, r0+1 -------
        int warp = (blockIdx.x * 256 + threadIdx.x) >> 5;
        int lane = threadIdx.x & 31;
        int r0 = warp * 2;
        const float4* rowA = (const float4*)(emb + (size_t)r0 * D_DIM);
        const float4* rowB = (const float4*)(emb + (size_t)(r0 + 1) * D_DIM);

        float sa = 0.f, sb = 0.f;
#pragma unroll
        for (int k = 0; k < 4; k++) {
            float4 va = __ldcs(&rowA[lane + 32 * k]);
            float4 vb = __ldcs(&rowB[lane + 32 * k]);
            sa = fmaf(va.x, va.x, sa); sa = fmaf(va.y, va.y, sa);
            sa = fmaf(va.z, va.z, sa); sa = fmaf(va.w, va.w, sa);
            sb = fmaf(vb.x, vb.x, sb); sb = fmaf(vb.y, vb.y, sb);
            sb = fmaf(vb.z, vb.z, sb); sb = fmaf(vb.w, vb.w, sb);
            size_t ea = (size_t)r0 * D_DIM + (lane + 32 * k) * 4;
            *(uint2*)(g_eh + ea)         = pack_h4(va);
            *(uint2*)(g_eh + ea + D_DIM) = pack_h4(vb);
        }
#pragma unroll
        for (int off = 16; off; off >>= 1) {
            sa += __shfl_xor_sync(0xffffffffu, sa, off);
            sb += __shfl_xor_sync(0xffffffffu, sb, off);
        }
        if (lane == 0) {
            g_vinv[r0]     = 1.f / fmaxf(sqrtf(sa), EPS_F);
            g_vinv[r0 + 1] = 1.f / fmaxf(sqrtf(sb), EPS_F);
        }
        return;
    }

    // ------- prep role: single global pass, smem-staged transpose -------
    int blk = blockIdx.x - VBLKS;       // 0..511
    int b   = blk >> 7;                 // 4 batches x 128 s-tiles
    int s0  = (blk & 127) * ST;
    int t   = threadIdx.x;
    const float* P = preds + (size_t)b * D_DIM * 512 + s0;

    // stage the full [512 d x 4 s] tile (each thread 8 elements)
    int ss = t & 3, dr = t >> 2;        // ss 0..3, dr 0..63
#pragma unroll
    for (int d0 = 0; d0 < D_DIM; d0 += 64)
        tile[d0 + dr][ss] = P[(size_t)(d0 + dr) * 512 + ss];
    __syncthreads();

    // norms from smem
    float acc = 0.f;
#pragma unroll
    for (int d0 = 0; d0 < D_DIM; d0 += 64)
        { float x = tile[d0 + dr][ss]; acc = fmaf(x, x, acc); }
    part[dr][ss] = acc;
    __syncthreads();
    if (t < ST) {
        float n = 0.f;
#pragma unroll
        for (int i = 0; i < 64; i++) n += part[i][t];
        inv_s[t] = 1.f / fmaxf(sqrtf(n), EPS_F);
        int r = b * 512 + s0 + t;
        tgt_s[t] = clamp_idx(target[r]);
        g_best[r] = 0ull;
    }
    __syncthreads();

    // transposed writes: thread -> (seq row ss2, 4 consecutive d)
    int ss2  = t >> 6;                  // 0..3
    int dcol = (t & 63) * 4;            // 0..252 step 4
    float inv = inv_s[ss2];
    int r = b * 512 + s0 + ss2;
    const float* erow = emb + (size_t)tgt_s[ss2] * D_DIM;
#pragma unroll
    for (int d0 = 0; d0 < D_DIM; d0 += 256) {
        float4 o;
        __half hq[4];
        float* ov = &o.x;
#pragma unroll
        for (int j = 0; j < 4; j++) {
            float on = tile[d0 + dcol + j][ss2] * inv;
            ov[j] = on;
            hq[j] = __float2half_rn(on - erow[d0 + dcol + j]);
        }
        *(float4*)(g_outn + (size_t)r * D_DIM + d0 + dcol) = o;
        *(__half2*)(g_qh + (size_t)r * D_DIM + d0 + dcol)     = __halves2half2(hq[0], hq[1]);
        *(__half2*)(g_qh + (size_t)r * D_DIM + d0 + dcol + 2) = __halves2half2(hq[2], hq[3]);
    }
}

// ---------------------------------------------------------------------------
// Kernel 2: fp16 mma.sync GEMM, 3-stage cp.async (1 barrier/chunk), 2 CTAs/SM,
// XOR-swizzled SMEM, vinv prefetched pre-loop, fused argmax epilogue.
// CTA 128x160, warp tile 32x80.
// ---------------------------------------------------------------------------
__global__ void __launch_bounds__(256, 2) gemm_mma_kernel() {
    extern __shared__ char smem[];
    const uint32_t sb = smem_u32(smem);
    const int tid  = threadIdx.x;
    const int wid  = tid >> 5;
    const int lane = tid & 31;
    const int mblk = blockIdx.x * MT;
    const int nblk = blockIdx.y * NT;
    const int warp_m = (wid & 3) * 32;      // 4 warps along M
    const int warp_n = (wid >> 2) * 80;     // 2 warps along N

    const __half* Aqh = g_qh + (size_t)mblk * D_DIM;
    const __half* Beh = g_eh + (size_t)nblk * D_DIM;

    if (tid < NT) ((float*)(smem + V_OFF))[tid] = g_vinv[nblk + tid];

    auto load_chunk = [&](int slot, int ch) {
        int kc = ch * KC;
        uint32_t st = sb + slot * STAGE;
#pragma unroll
        for (int i = 0; i < 4; i++) {
            int s = tid + i * 256;
            int row = s >> 3, c = s & 7;
            cp16(st + A_OFF + swz(row, c), Aqh + (size_t)row * D_DIM + kc + c * 8);
        }
#pragma unroll
        for (int i = 0; i < 5; i++) {
            int s = tid + i * 256;
            int row = s >> 3, c = s & 7;
            cp16(st + B_OFF + swz(row, c), Beh + (size_t)row * D_DIM + kc + c * 8);
        }
    };

    float acc[2][10][4];
#pragma unroll
    for (int i = 0; i < 2; i++)
#pragma unroll
        for (int j = 0; j < 10; j++)
#pragma unroll
            for (int k = 0; k < 4; k++) acc[i][j][k] = 0.f;

    load_chunk(0, 0); CP_COMMIT();
    load_chunk(1, 1); CP_COMMIT();

    for (int it = 0; it < NCHUNK; it++) {
        if (it + 1 < NCHUNK) { CP_WAIT1(); } else { CP_WAIT0(); }
        __syncthreads();

        if (it + 2 < NCHUNK) {
            load_chunk((it + 2) % NSTAGE, it + 2);
            CP_COMMIT();
        }

        uint32_t st  = sb + (it % NSTAGE) * STAGE;
        uint32_t sa  = st + A_OFF;
        uint32_t sbm = st + B_OFF;
#pragma unroll
        for (int ks = 0; ks < 4; ks++) {
            int k = ks * 16;
            uint32_t a[2][4];
#pragma unroll
            for (int mi = 0; mi < 2; mi++) {
                int row = warp_m + mi * 16 + (lane & 15);
                int kch = (k >> 3) + (lane >> 4);
                ldsm_x4(sa + swz(row, kch), a[mi][0], a[mi][1], a[mi][2], a[mi][3]);
            }
#pragma unroll
            for (int bj = 0; bj < 5; bj++) {
                uint32_t b0[2], b1[2];
                int n   = warp_n + bj * 16 + (lane & 7) + ((lane >> 4) & 1) * 8;
                int kch = (k >> 3) + ((lane >> 3) & 1);
                ldsm_x4(sbm + swz(n, kch), b0[0], b0[1], b1[0], b1[1]);
#pragma unroll
                for (int mi = 0; mi < 2; mi++) {
                    mma16816(acc[mi][bj * 2],     a[mi], b0);
                    mma16816(acc[mi][bj * 2 + 1], a[mi], b1);
                }
            }
        }
    }
    const float* vin = (const float*)(smem + V_OFF);

#pragma unroll
    for (int mi = 0; mi < 2; mi++) {
        float bv0 = -1e30f, bv1 = -1e30f;
        int   bj0 = 0,      bj1 = 0;
#pragma unroll
        for (int nj = 0; nj < 10; nj++) {
            int c0 = warp_n + nj * 8 + 2 * (lane & 3);
            float v00 = acc[mi][nj][0] * vin[c0];
            float v01 = acc[mi][nj][1] * vin[c0 + 1];
            float v10 = acc[mi][nj][2] * vin[c0];
            float v11 = acc[mi][nj][3] * vin[c0 + 1];
            if (v00 > bv0) { bv0 = v00; bj0 = c0; }
            if (v01 > bv0) { bv0 = v01; bj0 = c0 + 1; }
            if (v10 > bv1) { bv1 = v10; bj1 = c0; }
            if (v11 > bv1) { bv1 = v11; bj1 = c0 + 1; }
        }
#pragma unroll
        for (int off = 1; off < 4; off <<= 1) {
            float o0 = __shfl_xor_sync(0xffffffffu, bv0, off);
            int   j0 = __shfl_xor_sync(0xffffffffu, bj0, off);
            float o1 = __shfl_xor_sync(0xffffffffu, bv1, off);
            int   j1 = __shfl_xor_sync(0xffffffffu, bj1, off);
            if (o0 > bv0 || (o0 == bv0 && j0 < bj0)) { bv0 = o0; bj0 = j0; }
            if (o1 > bv1 || (o1 == bv1 && j1 < bj1)) { bv1 = o1; bj1 = j1; }
        }
        if ((lane & 3) == 0) {
            int r0 = mblk + warp_m + mi * 16 + (lane >> 2);
            atomicMax(&g_best[r0],     enc_key(bv0, (unsigned)(nblk + bj0)));
            atomicMax(&g_best[r0 + 8], enc_key(bv1, (unsigned)(nblk + bj1)));
        }
    }
}

// ---------------------------------------------------------------------------
// Kernel 3: per-row hinge (warp/row, float4 gathers) + last-block reduction.
// ---------------------------------------------------------------------------
__global__ void __launch_bounds__(256) finalize_reduce_kernel(
        const float* __restrict__ emb,
        const int* __restrict__ target,
        const int* __restrict__ pad,
        float* __restrict__ out) {
    __shared__ int s_last;
    int r    = blockIdx.x * 8 + (threadIdx.x >> 5);
    int lane = threadIdx.x & 31;
    int t = clamp_idx(target[r]);
    unsigned long long key = g_best[r];
    int jm = clamp_idx((int)(0x7fffffffu - (unsigned)(key & 0xffffffffu)));

    const float4* on = (const float4*)(g_outn + (size_t)r * D_DIM);
    const float4* e1 = (const float4*)(emb + (size_t)t  * D_DIM);
    const float4* e2 = (const float4*)(emb + (size_t)jm * D_DIM);
    float d1 = 0.f, d2 = 0.f;
#pragma unroll
    for (int i = 0; i < 4; i++) {
        int idx = lane + i * 32;
        float4 o = on[idx], a = __ldg(&e1[idx]), b2 = __ldg(&e2[idx]);
        d1 = fmaf(o.x, a.x, d1);  d1 = fmaf(o.y, a.y, d1);
        d1 = fmaf(o.z, a.z, d1);  d1 = fmaf(o.w, a.w, d1);
        d2 = fmaf(o.x, b2.x, d2); d2 = fmaf(o.y, b2.y, d2);
        d2 = fmaf(o.z, b2.z, d2); d2 = fmaf(o.w, b2.w, d2);
    }
#pragma unroll
    for (int off = 16; off; off >>= 1) {
        d1 += __shfl_xor_sync(0xffffffffu, d1, off);
        d2 += __shfl_xor_sync(0xffffffffu, d2, off);
    }
    if (lane == 0) {
        d1 *= g_vinv[t];
        d2 *= g_vinv[jm];
        float df = fmaxf(GAMMA_F + d2 - d1, 0.f);
        g_diff[r] = (target[r] != *pad) ? df : 0.f;
    }
    __threadfence();
    __syncthreads();
    if (threadIdx.x == 0)
        s_last = (atomicAdd(&g_cnt, 1) == (int)gridDim.x - 1) ? 1 : 0;
    __syncthreads();
    if (!s_last) return;

    __shared__ float ssum[256];
    __shared__ float scnt[256];
    int tt = threadIdx.x;
    int p = *pad;
    float s = 0.f, c = 0.f;
    for (int rr = tt; rr < BS_ROWS; rr += 256) {
        s += g_diff[rr];
        c += (target[rr] != p) ? 1.f : 0.f;
    }
    ssum[tt] = s; scnt[tt] = c; __syncthreads();
    for (int off = 128; off; off >>= 1) {
        if (tt < off) { ssum[tt] += ssum[tt + off]; scnt[tt] += scnt[tt + off]; }
        __syncthreads();
    }
    if (tt == 0) {
        out[0] = ssum[0] / scnt[0];
        g_cnt = 0;   // self-reset for next graph replay
    }
}

// ---------------------------------------------------------------------------
extern "C" void kernel_launch(void* const* d_in, const int* in_sizes, int n_in,
                              void* d_out, int out_size) {
    const float* preds  = (const float*)d_in[0];
    const float* emb    = (const float*)d_in[1];
    const int*   target = (const int*)d_in[2];
    const int*   pad    = (const int*)d_in[3];

    cudaFuncSetAttribute(gemm_mma_kernel, cudaFuncAttributeMaxDynamicSharedMemorySize, SMEMSZ);

    pre_kernel<<<VBLKS + PBLKS, 256>>>(emb, preds, target);
    dim3 grid(BS_ROWS / MT, V_DIM / NT);   // (16, 200)
    gemm_mma_kernel<<<grid, 256, SMEMSZ>>>();
    finalize_reduce_kernel<<<BS_ROWS / 8, 256>>>(emb, target, pad, (float*)d_out);
}